// round 1
// baseline (speedup 1.0000x reference)
#include <cuda_runtime.h>
#include <cuda_fp16.h>
#include <stdint.h>

// ---------------- problem constants ----------------
#define EDGES   524288
#define NNODES  16384
#define HD      256
#define EIN     512
#define DD      1024

// ---------------- device scratch (no allocations allowed) ----------------
static __device__ int    g_idx64;                         // 1 if edge_idx is int64
static __device__ __half g_WT[1835008];                   // all weights, transposed [N][K], fp16
static __device__ __half g_hE[(size_t)EDGES * EIN];       // h_E converted to fp16
static __device__ __half g_Xa[(size_t)EDGES * HD];        // X1 (later reused as Y1)
static __device__ __half g_Xb[(size_t)EDGES * HD];        // X2 (later reused as Y2)
static __device__ float  g_dh[(size_t)NNODES * HD];       // scatter accumulator
static __device__ float  g_h [(size_t)NNODES * HD];       // post-LN1 h (fp32, residual)
static __device__ __half g_hh[(size_t)NNODES * HD];       // post-LN1 h (fp16, GEMM input)

// WT packing offsets (in halfs)
#define WOFF_M0 0         // [256][512]
#define WOFF_M1 131072    // [256][256]
#define WOFF_M2 196608    // [256][256]
#define WOFF_D0 262144    // [1024][256]
#define WOFF_D1 524288    // [1024][1024]
#define WOFF_D2 1572864   // [256][1024]

// ---------------- small helpers ----------------
__device__ __forceinline__ float gelu_f(float x) {
    return 0.5f * x * (1.0f + erff(x * 0.70710678118654752f));
}

__device__ __forceinline__ void cpasync16(uint32_t dst, const void* src) {
    asm volatile("cp.async.cg.shared.global [%0], [%1], 16;" :: "r"(dst), "l"(src) : "memory");
}
__device__ __forceinline__ void cp_commit() {
    asm volatile("cp.async.commit_group;" ::: "memory");
}

__device__ __forceinline__ void ldsm4(uint32_t* r, uint32_t addr) {
    asm volatile("ldmatrix.sync.aligned.m8n8.x4.shared.b16 {%0,%1,%2,%3}, [%4];"
                 : "=r"(r[0]), "=r"(r[1]), "=r"(r[2]), "=r"(r[3]) : "r"(addr));
}

__device__ __forceinline__ void mma16816(float* c, const uint32_t* a, const uint32_t* b) {
    asm volatile("mma.sync.aligned.m16n8k16.row.col.f32.f16.f16.f32 "
                 "{%0,%1,%2,%3}, {%4,%5,%6,%7}, {%8,%9}, {%0,%1,%2,%3};"
                 : "+f"(c[0]), "+f"(c[1]), "+f"(c[2]), "+f"(c[3])
                 : "r"(a[0]), "r"(a[1]), "r"(a[2]), "r"(a[3]), "r"(b[0]), "r"(b[1]));
}

// ---------------- prep kernels ----------------
__global__ void detect_idx_kernel(const int* p) {
    if (threadIdx.x == 0 && blockIdx.x == 0) {
        int is64 = 1;
        for (int i = 1; i < 512; i += 2)
            if (p[i] != 0) { is64 = 0; break; }
        g_idx64 = is64;
    }
}

// W [K,N] fp32 row-major  ->  WT [N,K] fp16 row-major
__global__ void prep_wt_kernel(const float* __restrict__ W, __half* __restrict__ WT, int K, int N) {
    long long idx = (long long)blockIdx.x * blockDim.x + threadIdx.x;
    if (idx >= (long long)K * N) return;
    int k = (int)(idx / N);
    int n = (int)(idx % N);
    WT[(long long)n * K + k] = __float2half(W[idx]);
}

__global__ void zero_kernel(float* p, size_t n4) {
    size_t i = (size_t)blockIdx.x * blockDim.x + threadIdx.x;
    if (i < n4) ((float4*)p)[i] = make_float4(0.f, 0.f, 0.f, 0.f);
}

__global__ void cvt_f2h_kernel(const float* __restrict__ x, __half* __restrict__ y, size_t n8) {
    size_t i = (size_t)blockIdx.x * blockDim.x + threadIdx.x;
    if (i >= n8) return;
    const float4* xp = (const float4*)x;
    float4 a = xp[2 * i], b = xp[2 * i + 1];
    alignas(16) __half2 hs[4];
    hs[0] = __floats2half2_rn(a.x, a.y);
    hs[1] = __floats2half2_rn(a.z, a.w);
    hs[2] = __floats2half2_rn(b.x, b.y);
    hs[3] = __floats2half2_rn(b.z, b.w);
    *(uint4*)(y + 8 * i) = *(uint4*)hs;
}

// ---------------- LN1: h = LN(h_V + dh), also emit fp16 copy ----------------
__global__ void ln1_kernel(const float* __restrict__ hV, const float* __restrict__ dh,
                           const float* __restrict__ g1, const float* __restrict__ b1,
                           float* __restrict__ h, __half* __restrict__ hh) {
    int warp = threadIdx.x >> 5, lane = threadIdx.x & 31;
    int row = blockIdx.x * 8 + warp;
    float v[8];
    float s = 0.f, s2 = 0.f;
#pragma unroll
    for (int i = 0; i < 8; i++) {
        int c = lane + i * 32;
        v[i] = hV[(size_t)row * HD + c] + dh[(size_t)row * HD + c];
        s += v[i]; s2 += v[i] * v[i];
    }
#pragma unroll
    for (int off = 16; off; off >>= 1) {
        s  += __shfl_xor_sync(0xffffffffu, s, off);
        s2 += __shfl_xor_sync(0xffffffffu, s2, off);
    }
    float mu = s * (1.0f / HD);
    float var = s2 * (1.0f / HD) - mu * mu;
    float rs = rsqrtf(var + 1e-5f);
#pragma unroll
    for (int i = 0; i < 8; i++) {
        int c = lane + i * 32;
        float y = (v[i] - mu) * rs * g1[c] + b1[c];
        h [(size_t)row * HD + c] = y;
        hh[(size_t)row * HD + c] = __float2half(y);
    }
}

// ---------------- main GEMM ----------------
// D[128 x 256] = A[128 x K] * WT^T  (WT is [N,K] fp16, row-major)
#define BM 128
#define BN 256
#define BK 32
#define ASTR 40                    // BK + 8 halfs, kills ldmatrix bank conflicts
#define SM_A_BYTES (2 * BM * ASTR * 2)   // 20480
#define SM_B_BYTES (2 * BN * ASTR * 2)   // 40960
#define SMEM_MMA   (SM_A_BYTES + SM_B_BYTES)  // 61440
#define SMEM_LN2   (128 * 264 * 4)            // 135168

#define EPI_GELU    0
#define EPI_SCATTER 1
#define EPI_LN2     2

template <int K, int EPI>
__global__ void __launch_bounds__(256, 1)
gemm_kernel(const __half* __restrict__ A, const __half* __restrict__ WT_full,
            const float* __restrict__ bias_full,
            __half* __restrict__ out, int ldout,
            const float* __restrict__ h_res, const float* __restrict__ ln_g,
            const float* __restrict__ ln_b, float* __restrict__ outf,
            const void* __restrict__ eidx, float* __restrict__ dh) {
    extern __shared__ char smem[];
    __half* As = (__half*)smem;
    __half* Bs = (__half*)(smem + SM_A_BYTES);
    const int tid = threadIdx.x;
    const int m0  = blockIdx.x * BM;
    const int n0g = blockIdx.y * BN;
    const __half* WT  = WT_full + (size_t)n0g * K;
    const float* bias = bias_full + n0g;

    const uint32_t sA = (uint32_t)__cvta_generic_to_shared(As);
    const uint32_t sB = (uint32_t)__cvta_generic_to_shared(Bs);

    const int lane = tid & 31, warp = tid >> 5;
    const int wm = warp & 3, wn = warp >> 2;      // 4 m-warps x 2 n-warps
    const int ml = lane & 7, tl = lane >> 3;      // ldmatrix addressing

    auto issue_chunk = [&](int kc, int buf) {
#pragma unroll
        for (int i = 0; i < 2; i++) {            // A: 128 rows x 64B
            int idx = tid + i * 256;
            int r = idx >> 2, q = idx & 3;
            uint32_t dst = sA + (uint32_t)(((buf * BM + r) * ASTR + q * 8) * 2);
            cpasync16(dst, A + (size_t)(m0 + r) * K + kc * BK + q * 8);
        }
#pragma unroll
        for (int i = 0; i < 4; i++) {            // B: 256 rows x 64B
            int idx = tid + i * 256;
            int r = idx >> 2, q = idx & 3;
            uint32_t dst = sB + (uint32_t)(((buf * BN + r) * ASTR + q * 8) * 2);
            cpasync16(dst, WT + (size_t)r * K + kc * BK + q * 8);
        }
        cp_commit();
    };

    float acc[2][16][4];
#pragma unroll
    for (int mi = 0; mi < 2; mi++)
#pragma unroll
        for (int ni = 0; ni < 16; ni++)
#pragma unroll
            for (int j = 0; j < 4; j++) acc[mi][ni][j] = 0.f;

    const int NC = K / BK;
    issue_chunk(0, 0);

    for (int c = 0; c < NC; c++) {
        const int buf = c & 1;
        if (c + 1 < NC) {
            issue_chunk(c + 1, buf ^ 1);
            asm volatile("cp.async.wait_group 1;" ::: "memory");
        } else {
            asm volatile("cp.async.wait_group 0;" ::: "memory");
        }
        __syncthreads();
#pragma unroll
        for (int ks = 0; ks < 2; ks++) {
            const int kofs = ks * 16;
            uint32_t afr[2][4];
#pragma unroll
            for (int mi = 0; mi < 2; mi++) {
                int row = wm * 32 + mi * 16 + ml + (tl & 1) * 8;
                int col = kofs + (tl >> 1) * 8;
                ldsm4(afr[mi], sA + (uint32_t)(((buf * BM + row) * ASTR + col) * 2));
            }
#pragma unroll
            for (int j = 0; j < 8; j++) {
                uint32_t bfr[4];
                int rn  = wn * 128 + j * 16 + ml + (tl >> 1) * 8;
                int col = kofs + (tl & 1) * 8;
                ldsm4(bfr, sB + (uint32_t)(((buf * BN + rn) * ASTR + col) * 2));
#pragma unroll
                for (int mi = 0; mi < 2; mi++) {
                    mma16816(acc[mi][2 * j],     afr[mi], bfr);
                    mma16816(acc[mi][2 * j + 1], afr[mi], bfr + 2);
                }
            }
        }
        __syncthreads();
    }

    // ---------------- epilogues ----------------
    const int g  = lane >> 2;
    const int t2 = (lane & 3) * 2;

    if constexpr (EPI == EPI_GELU) {
#pragma unroll
        for (int mi = 0; mi < 2; mi++) {
            const int r0 = wm * 32 + mi * 16 + g;
#pragma unroll
            for (int ni = 0; ni < 16; ni++) {
                const int col = wn * 128 + ni * 8 + t2;
                const float b0v = bias[col], b1v = bias[col + 1];
                float x0 = gelu_f(acc[mi][ni][0] + b0v);
                float x1 = gelu_f(acc[mi][ni][1] + b1v);
                *(__half2*)(out + (size_t)(m0 + r0) * ldout + n0g + col) = __floats2half2_rn(x0, x1);
                float x2 = gelu_f(acc[mi][ni][2] + b0v);
                float x3 = gelu_f(acc[mi][ni][3] + b1v);
                *(__half2*)(out + (size_t)(m0 + r0 + 8) * ldout + n0g + col) = __floats2half2_rn(x2, x3);
            }
        }
    } else if constexpr (EPI == EPI_SCATTER) {
        const int is64 = g_idx64;
        const float inv_scale = 1.0f / 30.0f;
#pragma unroll
        for (int mi = 0; mi < 2; mi++) {
            const int r0 = wm * 32 + mi * 16 + g;
            const long long e0 = m0 + r0, e1 = e0 + 8;
            long long node0, node1;
            if (is64) {
                node0 = ((const long long*)eidx)[e0];
                node1 = ((const long long*)eidx)[e1];
            } else {
                node0 = ((const int*)eidx)[e0];
                node1 = ((const int*)eidx)[e1];
            }
            float* p0 = dh + node0 * HD;
            float* p1 = dh + node1 * HD;
#pragma unroll
            for (int ni = 0; ni < 16; ni++) {
                const int col = wn * 128 + ni * 8 + t2;
                const float b0v = bias[col], b1v = bias[col + 1];
                atomicAdd(p0 + col,     gelu_f(acc[mi][ni][0] + b0v) * inv_scale);
                atomicAdd(p0 + col + 1, gelu_f(acc[mi][ni][1] + b1v) * inv_scale);
                atomicAdd(p1 + col,     gelu_f(acc[mi][ni][2] + b0v) * inv_scale);
                atomicAdd(p1 + col + 1, gelu_f(acc[mi][ni][3] + b1v) * inv_scale);
            }
        }
    } else {  // EPI_LN2: out = LN(h + (acc + b2))
        float* sb = (float*)smem;  // [128][264], reuses As/Bs (dead after k-loop)
#pragma unroll
        for (int mi = 0; mi < 2; mi++) {
            const int r0 = wm * 32 + mi * 16 + g;
#pragma unroll
            for (int ni = 0; ni < 16; ni++) {
                const int col = wn * 128 + ni * 8 + t2;
                const float b0v = bias[col], b1v = bias[col + 1];
                sb[r0 * 264 + col]       = acc[mi][ni][0] + b0v + h_res[(size_t)(m0 + r0) * HD + col];
                sb[r0 * 264 + col + 1]   = acc[mi][ni][1] + b1v + h_res[(size_t)(m0 + r0) * HD + col + 1];
                sb[(r0 + 8) * 264 + col]     = acc[mi][ni][2] + b0v + h_res[(size_t)(m0 + r0 + 8) * HD + col];
                sb[(r0 + 8) * 264 + col + 1] = acc[mi][ni][3] + b1v + h_res[(size_t)(m0 + r0 + 8) * HD + col + 1];
            }
        }
        __syncthreads();
        for (int rr = 0; rr < 16; rr++) {
            const int row = warp * 16 + rr;
            float s = 0.f, s2 = 0.f;
#pragma unroll
            for (int i = 0; i < 8; i++) {
                float v = sb[row * 264 + lane + i * 32];
                s += v; s2 += v * v;
            }
#pragma unroll
            for (int off = 16; off; off >>= 1) {
                s  += __shfl_xor_sync(0xffffffffu, s, off);
                s2 += __shfl_xor_sync(0xffffffffu, s2, off);
            }
            const float mu  = s * (1.0f / HD);
            const float var = s2 * (1.0f / HD) - mu * mu;
            const float rs  = rsqrtf(var + 1e-5f);
#pragma unroll
            for (int i = 0; i < 8; i++) {
                const int ccol = lane + i * 32;
                const float v = sb[row * 264 + ccol];
                outf[(size_t)(m0 + row) * HD + ccol] = (v - mu) * rs * ln_g[ccol] + ln_b[ccol];
            }
        }
    }
}

// ---------------- host launcher ----------------
extern "C" void kernel_launch(void* const* d_in, const int* in_sizes, int n_in,
                              void* d_out, int out_size) {
    const float* h_V   = (const float*)d_in[0];
    const float* h_E   = (const float*)d_in[1];
    const void*  eidx  = d_in[2];
    const float* m0w   = (const float*)d_in[3];
    const float* m0b   = (const float*)d_in[4];
    const float* m1w   = (const float*)d_in[5];
    const float* m1b   = (const float*)d_in[6];
    const float* m2w   = (const float*)d_in[7];
    const float* m2b   = (const float*)d_in[8];
    const float* d0w   = (const float*)d_in[9];
    const float* d0b   = (const float*)d_in[10];
    const float* d1w   = (const float*)d_in[11];
    const float* d1b   = (const float*)d_in[12];
    const float* d2w   = (const float*)d_in[13];
    const float* d2b   = (const float*)d_in[14];
    const float* ln1g  = (const float*)d_in[15];
    const float* ln1b  = (const float*)d_in[16];
    const float* ln2g  = (const float*)d_in[17];
    const float* ln2b  = (const float*)d_in[18];
    float* outf = (float*)d_out;
    (void)n_in; (void)out_size; (void)in_sizes;

    // device scratch addresses (every call; no static caching allowed)
    void *pWT, *pHE, *pXa, *pXb, *pDH, *pH, *pHH;
    cudaGetSymbolAddress(&pWT, g_WT);
    cudaGetSymbolAddress(&pHE, g_hE);
    cudaGetSymbolAddress(&pXa, g_Xa);
    cudaGetSymbolAddress(&pXb, g_Xb);
    cudaGetSymbolAddress(&pDH, g_dh);
    cudaGetSymbolAddress(&pH,  g_h);
    cudaGetSymbolAddress(&pHH, g_hh);
    __half* WT = (__half*)pWT;
    __half* hE = (__half*)pHE;
    __half* Xa = (__half*)pXa;
    __half* Xb = (__half*)pXb;
    float*  dh = (float*)pDH;
    float*  hb = (float*)pH;
    __half* hh = (__half*)pHH;

    // allow >48KB dynamic smem (idempotent; done every call)
    cudaFuncSetAttribute(gemm_kernel<512,  EPI_GELU>,    cudaFuncAttributeMaxDynamicSharedMemorySize, SMEM_MMA);
    cudaFuncSetAttribute(gemm_kernel<256,  EPI_GELU>,    cudaFuncAttributeMaxDynamicSharedMemorySize, SMEM_MMA);
    cudaFuncSetAttribute(gemm_kernel<256,  EPI_SCATTER>, cudaFuncAttributeMaxDynamicSharedMemorySize, SMEM_MMA);
    cudaFuncSetAttribute(gemm_kernel<1024, EPI_GELU>,    cudaFuncAttributeMaxDynamicSharedMemorySize, SMEM_MMA);
    cudaFuncSetAttribute(gemm_kernel<1024, EPI_LN2>,     cudaFuncAttributeMaxDynamicSharedMemorySize, SMEM_LN2);

    // --- prep ---
    detect_idx_kernel<<<1, 32>>>((const int*)eidx);
    prep_wt_kernel<<<(512  * 256  + 255) / 256, 256>>>(m0w, WT + WOFF_M0, 512,  256);
    prep_wt_kernel<<<(256  * 256  + 255) / 256, 256>>>(m1w, WT + WOFF_M1, 256,  256);
    prep_wt_kernel<<<(256  * 256  + 255) / 256, 256>>>(m2w, WT + WOFF_M2, 256,  256);
    prep_wt_kernel<<<(256  * 1024 + 255) / 256, 256>>>(d0w, WT + WOFF_D0, 256,  1024);
    prep_wt_kernel<<<(1024 * 1024 + 255) / 256, 256>>>(d1w, WT + WOFF_D1, 1024, 1024);
    prep_wt_kernel<<<(1024 * 256  + 255) / 256, 256>>>(d2w, WT + WOFF_D2, 1024, 256);
    zero_kernel<<<(NNODES * HD / 4 + 255) / 256, 256>>>(dh, (size_t)NNODES * HD / 4);
    cvt_f2h_kernel<<<(int)(((size_t)EDGES * EIN / 8 + 255) / 256), 256>>>(h_E, hE, (size_t)EDGES * EIN / 8);

    // --- edge MLP ---
    gemm_kernel<512, EPI_GELU><<<dim3(EDGES / BM, 1), 256, SMEM_MMA>>>(
        hE, WT + WOFF_M0, m0b, Xa, HD, nullptr, nullptr, nullptr, nullptr, nullptr, nullptr);
    gemm_kernel<256, EPI_GELU><<<dim3(EDGES / BM, 1), 256, SMEM_MMA>>>(
        Xa, WT + WOFF_M1, m1b, Xb, HD, nullptr, nullptr, nullptr, nullptr, nullptr, nullptr);
    gemm_kernel<256, EPI_SCATTER><<<dim3(EDGES / BM, 1), 256, SMEM_MMA>>>(
        Xb, WT + WOFF_M2, m2b, nullptr, 0, nullptr, nullptr, nullptr, nullptr, eidx, dh);

    // --- LN1 ---
    ln1_kernel<<<NNODES / 8, 256>>>(h_V, dh, ln1g, ln1b, hb, hh);

    // --- dense MLP (Y1 reuses Xa, Y2 reuses Xb) ---
    gemm_kernel<256, EPI_GELU><<<dim3(NNODES / BM, 4), 256, SMEM_MMA>>>(
        hh, WT + WOFF_D0, d0b, Xa, DD, nullptr, nullptr, nullptr, nullptr, nullptr, nullptr);
    gemm_kernel<1024, EPI_GELU><<<dim3(NNODES / BM, 4), 256, SMEM_MMA>>>(
        Xa, WT + WOFF_D1, d1b, Xb, DD, nullptr, nullptr, nullptr, nullptr, nullptr, nullptr);
    gemm_kernel<1024, EPI_LN2><<<dim3(NNODES / BM, 1), 256, SMEM_LN2>>>(
        Xb, WT + WOFF_D2, d2b, nullptr, 0, hb, ln2g, ln2b, outf, nullptr, nullptr);
}

// round 4
// speedup vs baseline: 1.0519x; 1.0519x over previous
#include <cuda_runtime.h>
#include <cuda_fp16.h>
#include <stdint.h>

// ---------------- problem constants ----------------
#define EDGES   524288
#define NNODES  16384
#define HD      256
#define EIN     512
#define DD      1024

// ---------------- device scratch (no allocations allowed) ----------------
static __device__ int    g_idx64;
static __device__ __half g_WT[1835008];                   // all weights, [N][K] fp16
static __device__ __half g_Xa[(size_t)EDGES * HD];
static __device__ __half g_Xb[(size_t)EDGES * HD];
static __device__ float  g_h [(size_t)NNODES * HD];       // post-LN1 h (fp32 residual)
static __device__ __half g_hh[(size_t)NNODES * HD];       // post-LN1 h (fp16)
// CSR structures
static __device__ int    g_cnt[NNODES];
static __device__ int    g_off[NNODES + 1];
static __device__ int    g_cur[NNODES];
static __device__ int    g_elist[EDGES];

#define WOFF_M0 0         // [256][512]
#define WOFF_M1 131072    // [256][256]
#define WOFF_M2 196608    // [256][256]
#define WOFF_D0 262144    // [1024][256]
#define WOFF_D1 524288    // [1024][1024]
#define WOFF_D2 1572864   // [256][1024]

// ---------------- helpers ----------------
__device__ __forceinline__ float gelu_f(float x) {
    return 0.5f * x * (1.0f + erff(x * 0.70710678118654752f));
}
__device__ __forceinline__ void cpasync16(uint32_t dst, const void* src) {
    asm volatile("cp.async.cg.shared.global [%0], [%1], 16;" :: "r"(dst), "l"(src) : "memory");
}
__device__ __forceinline__ void cp_commit() {
    asm volatile("cp.async.commit_group;" ::: "memory");
}
__device__ __forceinline__ void ldsm4(uint32_t* r, uint32_t addr) {
    asm volatile("ldmatrix.sync.aligned.m8n8.x4.shared.b16 {%0,%1,%2,%3}, [%4];"
                 : "=r"(r[0]), "=r"(r[1]), "=r"(r[2]), "=r"(r[3]) : "r"(addr));
}
__device__ __forceinline__ void mma16816(float* c, const uint32_t* a, const uint32_t* b) {
    asm volatile("mma.sync.aligned.m16n8k16.row.col.f32.f16.f16.f32 "
                 "{%0,%1,%2,%3}, {%4,%5,%6,%7}, {%8,%9}, {%0,%1,%2,%3};"
                 : "+f"(c[0]), "+f"(c[1]), "+f"(c[2]), "+f"(c[3])
                 : "r"(a[0]), "r"(a[1]), "r"(a[2]), "r"(a[3]), "r"(b[0]), "r"(b[1]));
}

// ---------------- prep kernels ----------------
__global__ void detect_idx_kernel(const int* p) {
    if (threadIdx.x == 0 && blockIdx.x == 0) {
        int is64 = 1;
        for (int i = 1; i < 512; i += 2)
            if (p[i] != 0) { is64 = 0; break; }
        g_idx64 = is64;
    }
}

// W [K,N] fp32 row-major -> WT [N,K] fp16 row-major
__global__ void prep_wt_kernel(const float* __restrict__ W, __half* __restrict__ WT, int K, int N) {
    long long idx = (long long)blockIdx.x * blockDim.x + threadIdx.x;
    if (idx >= (long long)K * N) return;
    int k = (int)(idx / N);
    int n = (int)(idx % N);
    WT[(long long)n * K + k] = __float2half(W[idx]);
}

// ---------------- CSR build ----------------
__global__ void zero_cnt_kernel() {
    int i = blockIdx.x * 256 + threadIdx.x;
    if (i < NNODES) g_cnt[i] = 0;
}
__global__ void count_kernel(const void* __restrict__ eidx) {
    int e = blockIdx.x * 256 + threadIdx.x;
    int n = g_idx64 ? (int)((const long long*)eidx)[e] : ((const int*)eidx)[e];
    atomicAdd(&g_cnt[n], 1);
}
__global__ void scan_kernel() {
    __shared__ int part[1024];
    int t = threadIdx.x;
    int loc[16]; int s = 0;
#pragma unroll
    for (int i = 0; i < 16; i++) { loc[i] = g_cnt[t * 16 + i]; s += loc[i]; }
    part[t] = s;
    __syncthreads();
    for (int o = 1; o < 1024; o <<= 1) {
        int v = (t >= o) ? part[t - o] : 0;
        __syncthreads();
        part[t] += v;
        __syncthreads();
    }
    int run = (t == 0) ? 0 : part[t - 1];
#pragma unroll
    for (int i = 0; i < 16; i++) { g_off[t * 16 + i] = run; g_cur[t * 16 + i] = run; run += loc[i]; }
    if (t == 1023) g_off[NNODES] = run;
}
__global__ void fill_kernel(const void* __restrict__ eidx) {
    int e = blockIdx.x * 256 + threadIdx.x;
    int n = g_idx64 ? (int)((const long long*)eidx)[e] : ((const int*)eidx)[e];
    int pos = atomicAdd(&g_cur[n], 1);
    g_elist[pos] = e;
}

// ---------------- fused gather + LN1 ----------------
// h = LN(h_V + (sum_e m[e]) / 30), also emit fp16 copy. One block per node.
__global__ void gather_ln1_kernel(const __half* __restrict__ m,
                                  const float* __restrict__ hV,
                                  const float* __restrict__ g1, const float* __restrict__ b1,
                                  float* __restrict__ h, __half* __restrict__ hh) {
    __shared__ float sm1[8], sm2[8];
    const int n = blockIdx.x, c = threadIdx.x;
    const int wid = c >> 5, lane = c & 31;
    const int s = g_off[n], e = g_off[n + 1];
    float acc = 0.f;
    int i = s;
    for (; i + 4 <= e; i += 4) {
        int e0 = g_elist[i], e1 = g_elist[i + 1], e2 = g_elist[i + 2], e3 = g_elist[i + 3];
        acc += __half2float(m[(size_t)e0 * HD + c]);
        acc += __half2float(m[(size_t)e1 * HD + c]);
        acc += __half2float(m[(size_t)e2 * HD + c]);
        acc += __half2float(m[(size_t)e3 * HD + c]);
    }
    for (; i < e; i++)
        acc += __half2float(m[(size_t)g_elist[i] * HD + c]);

    const float v = hV[(size_t)n * HD + c] + acc * (1.0f / 30.0f);
    float s1 = v, s2 = v * v;
#pragma unroll
    for (int off = 16; off; off >>= 1) {
        s1 += __shfl_xor_sync(0xffffffffu, s1, off);
        s2 += __shfl_xor_sync(0xffffffffu, s2, off);
    }
    if (lane == 0) { sm1[wid] = s1; sm2[wid] = s2; }
    __syncthreads();
    float t1 = 0.f, t2 = 0.f;
#pragma unroll
    for (int k = 0; k < 8; k++) { t1 += sm1[k]; t2 += sm2[k]; }
    const float mu  = t1 * (1.0f / HD);
    const float var = t2 * (1.0f / HD) - mu * mu;
    const float rs  = rsqrtf(var + 1e-5f);
    const float y = (v - mu) * rs * g1[c] + b1[c];
    h [(size_t)n * HD + c] = y;
    hh[(size_t)n * HD + c] = __float2half(y);
}

// ---------------- main GEMM (mma.sync HMMA) ----------------
// D[128 x 256] = A[128 x K] * WT^T   (WT is [N,K] fp16 row-major)
#define BM 128
#define BN 256
#define BK 32
#define ASTR 40                          // BK + 8 halfs: ldmatrix conflict-free
#define SM_A_BYTES (2 * BM * ASTR * 2)   // 20480
#define SM_B_BYTES (2 * BN * ASTR * 2)   // 40960
#define SMEM_MMA   (SM_A_BYTES + SM_B_BYTES)  // 61440
#define SMEM_LN2   (128 * 264 * 4)            // 135168

#define EPI_GELU 0
#define EPI_LN2  2

// AF32: A operand is fp32 in gmem; convert in-register during the producer path.
template <int K, int EPI, bool AF32>
__global__ void __launch_bounds__(256, 1)
gemm_kernel(const void* __restrict__ Ain, const __half* __restrict__ WT_full,
            const float* __restrict__ bias_full,
            __half* __restrict__ out, int ldout,
            const float* __restrict__ h_res, const float* __restrict__ ln_g,
            const float* __restrict__ ln_b, float* __restrict__ outf) {
    extern __shared__ char smem[];
    __half* As = (__half*)smem;
    __half* Bs = (__half*)(smem + SM_A_BYTES);
    const int tid = threadIdx.x;
    const int m0  = blockIdx.x * BM;
    const int n0g = blockIdx.y * BN;
    const __half* WT  = WT_full + (size_t)n0g * K;
    const float* bias = bias_full + n0g;
    const __half* Ah  = (const __half*)Ain;
    const float*  Af  = (const float*)Ain;

    const uint32_t sA = (uint32_t)__cvta_generic_to_shared(As);
    const uint32_t sB = (uint32_t)__cvta_generic_to_shared(Bs);

    const int lane = tid & 31, warp = tid >> 5;
    const int wm = warp & 3, wn = warp >> 2;      // 4 m-warps x 2 n-warps
    const int ml = lane & 7, tl = lane >> 3;

    // fp32-A register prefetch state (2 groups of 8 halfs per thread)
    float4 ra[2][2];
    auto ldgA = [&](int kc) {
        if constexpr (AF32) {
#pragma unroll
            for (int g = 0; g < 2; g++) {
                int gi = tid + g * 256;
                int r = gi >> 2, q = gi & 3;
                const float4* p = (const float4*)(Af + (size_t)(m0 + r) * K + kc * BK + q * 8);
                ra[g][0] = p[0];
                ra[g][1] = p[1];
            }
        }
    };
    auto stsA = [&](int buf) {
        if constexpr (AF32) {
#pragma unroll
            for (int g = 0; g < 2; g++) {
                int gi = tid + g * 256;
                int r = gi >> 2, q = gi & 3;
                alignas(16) __half2 hv[4];
                hv[0] = __floats2half2_rn(ra[g][0].x, ra[g][0].y);
                hv[1] = __floats2half2_rn(ra[g][0].z, ra[g][0].w);
                hv[2] = __floats2half2_rn(ra[g][1].x, ra[g][1].y);
                hv[3] = __floats2half2_rn(ra[g][1].z, ra[g][1].w);
                *(uint4*)(As + (buf * BM + r) * ASTR + q * 8) = *(uint4*)hv;
            }
        }
    };
    auto issue_tile = [&](int kc, int buf) {
        if constexpr (!AF32) {
#pragma unroll
            for (int i = 0; i < 2; i++) {            // A: 128 rows x 64B
                int idx = tid + i * 256;
                int r = idx >> 2, q = idx & 3;
                uint32_t dst = sA + (uint32_t)(((buf * BM + r) * ASTR + q * 8) * 2);
                cpasync16(dst, Ah + (size_t)(m0 + r) * K + kc * BK + q * 8);
            }
        }
#pragma unroll
        for (int i = 0; i < 4; i++) {                // B: 256 rows x 64B
            int idx = tid + i * 256;
            int r = idx >> 2, q = idx & 3;
            uint32_t dst = sB + (uint32_t)(((buf * BN + r) * ASTR + q * 8) * 2);
            cpasync16(dst, WT + (size_t)r * K + kc * BK + q * 8);
        }
        cp_commit();
    };

    float acc[2][16][4];
#pragma unroll
    for (int mi = 0; mi < 2; mi++)
#pragma unroll
        for (int ni = 0; ni < 16; ni++)
#pragma unroll
            for (int j = 0; j < 4; j++) acc[mi][ni][j] = 0.f;

    const int NC = K / BK;
    ldgA(0);
    issue_tile(0, 0);

    for (int c = 0; c < NC; c++) {
        const int buf = c & 1;
        if (c + 1 < NC) {
            issue_tile(c + 1, buf ^ 1);
            asm volatile("cp.async.wait_group 1;" ::: "memory");
        } else {
            asm volatile("cp.async.wait_group 0;" ::: "memory");
        }
        stsA(buf);               // AF32: write A chunk c (regs loaded during c-1)
        if (c + 1 < NC) ldgA(c + 1);   // AF32: prefetch next, hidden under mma
        __syncthreads();
#pragma unroll
        for (int ks = 0; ks < 2; ks++) {
            const int kofs = ks * 16;
            uint32_t afr[2][4];
#pragma unroll
            for (int mi = 0; mi < 2; mi++) {
                int row = wm * 32 + mi * 16 + ml + (tl & 1) * 8;
                int col = kofs + (tl >> 1) * 8;
                ldsm4(afr[mi], sA + (uint32_t)(((buf * BM + row) * ASTR + col) * 2));
            }
#pragma unroll
            for (int j = 0; j < 8; j++) {
                uint32_t bfr[4];
                int rn  = wn * 128 + j * 16 + ml + (tl >> 1) * 8;
                int col = kofs + (tl & 1) * 8;
                ldsm4(bfr, sB + (uint32_t)(((buf * BN + rn) * ASTR + col) * 2));
#pragma unroll
                for (int mi = 0; mi < 2; mi++) {
                    mma16816(acc[mi][2 * j],     afr[mi], bfr);
                    mma16816(acc[mi][2 * j + 1], afr[mi], bfr + 2);
                }
            }
        }
        __syncthreads();
    }

    // ---------------- epilogues ----------------
    const int g  = lane >> 2;
    const int t2 = (lane & 3) * 2;

    if constexpr (EPI == EPI_GELU) {
#pragma unroll
        for (int mi = 0; mi < 2; mi++) {
            const int r0 = wm * 32 + mi * 16 + g;
#pragma unroll
            for (int ni = 0; ni < 16; ni++) {
                const int col = wn * 128 + ni * 8 + t2;
                const float b0v = bias[col], b1v = bias[col + 1];
                float x0 = gelu_f(acc[mi][ni][0] + b0v);
                float x1 = gelu_f(acc[mi][ni][1] + b1v);
                *(__half2*)(out + (size_t)(m0 + r0) * ldout + n0g + col) = __floats2half2_rn(x0, x1);
                float x2 = gelu_f(acc[mi][ni][2] + b0v);
                float x3 = gelu_f(acc[mi][ni][3] + b1v);
                *(__half2*)(out + (size_t)(m0 + r0 + 8) * ldout + n0g + col) = __floats2half2_rn(x2, x3);
            }
        }
    } else {  // EPI_LN2: out = LN(h + acc + b2)
        float* sb = (float*)smem;  // [128][264]
#pragma unroll
        for (int mi = 0; mi < 2; mi++) {
            const int r0 = wm * 32 + mi * 16 + g;
#pragma unroll
            for (int ni = 0; ni < 16; ni++) {
                const int col = wn * 128 + ni * 8 + t2;
                const float b0v = bias[col], b1v = bias[col + 1];
                sb[r0 * 264 + col]           = acc[mi][ni][0] + b0v + h_res[(size_t)(m0 + r0) * HD + col];
                sb[r0 * 264 + col + 1]       = acc[mi][ni][1] + b1v + h_res[(size_t)(m0 + r0) * HD + col + 1];
                sb[(r0 + 8) * 264 + col]     = acc[mi][ni][2] + b0v + h_res[(size_t)(m0 + r0 + 8) * HD + col];
                sb[(r0 + 8) * 264 + col + 1] = acc[mi][ni][3] + b1v + h_res[(size_t)(m0 + r0 + 8) * HD + col + 1];
            }
        }
        __syncthreads();
        for (int rr = 0; rr < 16; rr++) {
            const int row = warp * 16 + rr;
            float s = 0.f, s2 = 0.f;
#pragma unroll
            for (int i = 0; i < 8; i++) {
                float v = sb[row * 264 + lane + i * 32];
                s += v; s2 += v * v;
            }
#pragma unroll
            for (int off = 16; off; off >>= 1) {
                s  += __shfl_xor_sync(0xffffffffu, s, off);
                s2 += __shfl_xor_sync(0xffffffffu, s2, off);
            }
            const float mu  = s * (1.0f / HD);
            const float var = s2 * (1.0f / HD) - mu * mu;
            const float rs  = rsqrtf(var + 1e-5f);
#pragma unroll
            for (int i = 0; i < 8; i++) {
                const int cc = lane + i * 32;
                const float v = sb[row * 264 + cc];
                outf[(size_t)(m0 + row) * HD + cc] = (v - mu) * rs * ln_g[cc] + ln_b[cc];
            }
        }
    }
}

// ---------------- host launcher ----------------
extern "C" void kernel_launch(void* const* d_in, const int* in_sizes, int n_in,
                              void* d_out, int out_size) {
    const float* h_V  = (const float*)d_in[0];
    const float* h_E  = (const float*)d_in[1];
    const void*  eidx = d_in[2];
    const float* m0w  = (const float*)d_in[3];
    const float* m0b  = (const float*)d_in[4];
    const float* m1w  = (const float*)d_in[5];
    const float* m1b  = (const float*)d_in[6];
    const float* m2w  = (const float*)d_in[7];
    const float* m2b  = (const float*)d_in[8];
    const float* d0w  = (const float*)d_in[9];
    const float* d0b  = (const float*)d_in[10];
    const float* d1w  = (const float*)d_in[11];
    const float* d1b  = (const float*)d_in[12];
    const float* d2w  = (const float*)d_in[13];
    const float* d2b  = (const float*)d_in[14];
    const float* ln1g = (const float*)d_in[15];
    const float* ln1b = (const float*)d_in[16];
    const float* ln2g = (const float*)d_in[17];
    const float* ln2b = (const float*)d_in[18];
    float* outf = (float*)d_out;
    (void)n_in; (void)out_size; (void)in_sizes;

    void *pWT, *pXa, *pXb, *pH, *pHH;
    cudaGetSymbolAddress(&pWT, g_WT);
    cudaGetSymbolAddress(&pXa, g_Xa);
    cudaGetSymbolAddress(&pXb, g_Xb);
    cudaGetSymbolAddress(&pH,  g_h);
    cudaGetSymbolAddress(&pHH, g_hh);
    __half* WT = (__half*)pWT;
    __half* Xa = (__half*)pXa;
    __half* Xb = (__half*)pXb;
    float*  hb = (float*)pH;
    __half* hh = (__half*)pHH;

    cudaFuncSetAttribute(gemm_kernel<512,  EPI_GELU, true>,  cudaFuncAttributeMaxDynamicSharedMemorySize, SMEM_MMA);
    cudaFuncSetAttribute(gemm_kernel<256,  EPI_GELU, false>, cudaFuncAttributeMaxDynamicSharedMemorySize, SMEM_MMA);
    cudaFuncSetAttribute(gemm_kernel<1024, EPI_GELU, false>, cudaFuncAttributeMaxDynamicSharedMemorySize, SMEM_MMA);
    cudaFuncSetAttribute(gemm_kernel<1024, EPI_LN2,  false>, cudaFuncAttributeMaxDynamicSharedMemorySize, SMEM_LN2);

    // --- prep ---
    detect_idx_kernel<<<1, 32>>>((const int*)eidx);
    prep_wt_kernel<<<(512  * 256  + 255) / 256, 256>>>(m0w, WT + WOFF_M0, 512,  256);
    prep_wt_kernel<<<(256  * 256  + 255) / 256, 256>>>(m1w, WT + WOFF_M1, 256,  256);
    prep_wt_kernel<<<(256  * 256  + 255) / 256, 256>>>(m2w, WT + WOFF_M2, 256,  256);
    prep_wt_kernel<<<(256  * 1024 + 255) / 256, 256>>>(d0w, WT + WOFF_D0, 256,  1024);
    prep_wt_kernel<<<(1024 * 1024 + 255) / 256, 256>>>(d1w, WT + WOFF_D1, 1024, 1024);
    prep_wt_kernel<<<(1024 * 256  + 255) / 256, 256>>>(d2w, WT + WOFF_D2, 1024, 256);

    // --- CSR build ---
    zero_cnt_kernel<<<NNODES / 256, 256>>>();
    count_kernel<<<EDGES / 256, 256>>>(eidx);
    scan_kernel<<<1, 1024>>>();
    fill_kernel<<<EDGES / 256, 256>>>(eidx);

    // --- edge MLP (GEMM1 consumes fp32 h_E directly, converting in-flight) ---
    gemm_kernel<512, EPI_GELU, true><<<dim3(EDGES / BM, 1), 256, SMEM_MMA>>>(
        h_E, WT + WOFF_M0, m0b, Xa, HD, nullptr, nullptr, nullptr, nullptr);
    gemm_kernel<256, EPI_GELU, false><<<dim3(EDGES / BM, 1), 256, SMEM_MMA>>>(
        Xa, WT + WOFF_M1, m1b, Xb, HD, nullptr, nullptr, nullptr, nullptr);
    gemm_kernel<256, EPI_GELU, false><<<dim3(EDGES / BM, 1), 256, SMEM_MMA>>>(
        Xb, WT + WOFF_M2, m2b, Xa, HD, nullptr, nullptr, nullptr, nullptr);

    // --- scatter-sum via CSR gather, fused with LN1 ---
    gather_ln1_kernel<<<NNODES, 256>>>(Xa, h_V, ln1g, ln1b, hb, hh);

    // --- dense MLP ---
    gemm_kernel<256, EPI_GELU, false><<<dim3(NNODES / BM, 4), 256, SMEM_MMA>>>(
        hh, WT + WOFF_D0, d0b, Xb, DD, nullptr, nullptr, nullptr, nullptr);
    gemm_kernel<1024, EPI_GELU, false><<<dim3(NNODES / BM, 4), 256, SMEM_MMA>>>(
        Xb, WT + WOFF_D1, d1b, Xa, DD, nullptr, nullptr, nullptr, nullptr);
    gemm_kernel<1024, EPI_LN2, false><<<dim3(NNODES / BM, 1), 256, SMEM_LN2>>>(
        Xa, WT + WOFF_D2, d2b, nullptr, 0, hb, ln2g, ln2b, outf);
}

// round 5
// speedup vs baseline: 1.1740x; 1.1161x over previous
#include <cuda_runtime.h>
#include <cuda_fp16.h>
#include <stdint.h>

// ---------------- problem constants ----------------
#define EDGES   524288
#define NNODES  16384
#define HD      256
#define EIN     512
#define DD      1024

// ---------------- device scratch (no allocations allowed) ----------------
static __device__ int    g_idx64;
static __device__ __half g_WT[1835008];                   // all weights, [N][K] fp16
static __device__ __half g_Xa[(size_t)EDGES * HD];
static __device__ __half g_Xb[(size_t)EDGES * HD];
static __device__ float  g_h [(size_t)NNODES * HD];       // post-LN1 h (fp32 residual)
static __device__ __half g_hh[(size_t)NNODES * HD];       // post-LN1 h (fp16)
// CSR structures
static __device__ int    g_cnt[NNODES];
static __device__ int    g_off[NNODES + 1];
static __device__ int    g_cur[NNODES];
static __device__ int    g_elist[EDGES];

#define WOFF_M0 0         // [256][512]
#define WOFF_M1 131072    // [256][256]
#define WOFF_M2 196608    // [256][256]
#define WOFF_D0 262144    // [1024][256]
#define WOFF_D1 524288    // [1024][1024]
#define WOFF_D2 1572864   // [256][1024]

// ---------------- helpers ----------------
__device__ __forceinline__ float gelu_f(float x) {
    return 0.5f * x * (1.0f + erff(x * 0.70710678118654752f));
}
__device__ __forceinline__ void cpasync16(uint32_t dst, const void* src) {
    asm volatile("cp.async.cg.shared.global [%0], [%1], 16;" :: "r"(dst), "l"(src) : "memory");
}
__device__ __forceinline__ void cp_commit() {
    asm volatile("cp.async.commit_group;" ::: "memory");
}
__device__ __forceinline__ void ldsm4(uint32_t* r, uint32_t addr) {
    asm volatile("ldmatrix.sync.aligned.m8n8.x4.shared.b16 {%0,%1,%2,%3}, [%4];"
                 : "=r"(r[0]), "=r"(r[1]), "=r"(r[2]), "=r"(r[3]) : "r"(addr));
}
__device__ __forceinline__ void mma16816(float* c, const uint32_t* a, const uint32_t* b) {
    asm volatile("mma.sync.aligned.m16n8k16.row.col.f32.f16.f16.f32 "
                 "{%0,%1,%2,%3}, {%4,%5,%6,%7}, {%8,%9}, {%0,%1,%2,%3};"
                 : "+f"(c[0]), "+f"(c[1]), "+f"(c[2]), "+f"(c[3])
                 : "r"(a[0]), "r"(a[1]), "r"(a[2]), "r"(a[3]), "r"(b[0]), "r"(b[1]));
}

// ---------------- prep kernels ----------------
__global__ void detect_idx_kernel(const int* p) {
    if (threadIdx.x == 0 && blockIdx.x == 0) {
        int is64 = 1;
        for (int i = 1; i < 512; i += 2)
            if (p[i] != 0) { is64 = 0; break; }
        g_idx64 = is64;
    }
}

// W [K,N] fp32 row-major -> WT [N,K] fp16 row-major
__global__ void prep_wt_kernel(const float* __restrict__ W, __half* __restrict__ WT, int K, int N) {
    long long idx = (long long)blockIdx.x * blockDim.x + threadIdx.x;
    if (idx >= (long long)K * N) return;
    int k = (int)(idx / N);
    int n = (int)(idx % N);
    WT[(long long)n * K + k] = __float2half(W[idx]);
}

// ---------------- CSR build ----------------
__global__ void zero_cnt_kernel() {
    int i = blockIdx.x * 256 + threadIdx.x;
    if (i < NNODES) g_cnt[i] = 0;
}
__global__ void count_kernel(const void* __restrict__ eidx) {
    int e = blockIdx.x * 256 + threadIdx.x;
    int n = g_idx64 ? (int)((const long long*)eidx)[e] : ((const int*)eidx)[e];
    atomicAdd(&g_cnt[n], 1);
}
__global__ void scan_kernel() {
    __shared__ int part[1024];
    int t = threadIdx.x;
    int loc[16]; int s = 0;
#pragma unroll
    for (int i = 0; i < 16; i++) { loc[i] = g_cnt[t * 16 + i]; s += loc[i]; }
    part[t] = s;
    __syncthreads();
    for (int o = 1; o < 1024; o <<= 1) {
        int v = (t >= o) ? part[t - o] : 0;
        __syncthreads();
        part[t] += v;
        __syncthreads();
    }
    int run = (t == 0) ? 0 : part[t - 1];
#pragma unroll
    for (int i = 0; i < 16; i++) { g_off[t * 16 + i] = run; g_cur[t * 16 + i] = run; run += loc[i]; }
    if (t == 1023) g_off[NNODES] = run;
}
__global__ void fill_kernel(const void* __restrict__ eidx) {
    int e = blockIdx.x * 256 + threadIdx.x;
    int n = g_idx64 ? (int)((const long long*)eidx)[e] : ((const int*)eidx)[e];
    int pos = atomicAdd(&g_cur[n], 1);
    g_elist[pos] = e;
}

// ---------------- fused gather + LN1 ----------------
__global__ void gather_ln1_kernel(const __half* __restrict__ m,
                                  const float* __restrict__ hV,
                                  const float* __restrict__ g1, const float* __restrict__ b1,
                                  float* __restrict__ h, __half* __restrict__ hh) {
    __shared__ float sm1[8], sm2[8];
    const int n = blockIdx.x, c = threadIdx.x;
    const int wid = c >> 5, lane = c & 31;
    const int s = g_off[n], e = g_off[n + 1];
    float acc = 0.f;
    int i = s;
    for (; i + 4 <= e; i += 4) {
        int e0 = g_elist[i], e1 = g_elist[i + 1], e2 = g_elist[i + 2], e3 = g_elist[i + 3];
        acc += __half2float(m[(size_t)e0 * HD + c]);
        acc += __half2float(m[(size_t)e1 * HD + c]);
        acc += __half2float(m[(size_t)e2 * HD + c]);
        acc += __half2float(m[(size_t)e3 * HD + c]);
    }
    for (; i < e; i++)
        acc += __half2float(m[(size_t)g_elist[i] * HD + c]);

    const float v = hV[(size_t)n * HD + c] + acc * (1.0f / 30.0f);
    float s1 = v, s2 = v * v;
#pragma unroll
    for (int off = 16; off; off >>= 1) {
        s1 += __shfl_xor_sync(0xffffffffu, s1, off);
        s2 += __shfl_xor_sync(0xffffffffu, s2, off);
    }
    if (lane == 0) { sm1[wid] = s1; sm2[wid] = s2; }
    __syncthreads();
    float t1 = 0.f, t2 = 0.f;
#pragma unroll
    for (int k = 0; k < 8; k++) { t1 += sm1[k]; t2 += sm2[k]; }
    const float mu  = t1 * (1.0f / HD);
    const float var = t2 * (1.0f / HD) - mu * mu;
    const float rs  = rsqrtf(var + 1e-5f);
    const float y = (v - mu) * rs * g1[c] + b1[c];
    h [(size_t)n * HD + c] = y;
    hh[(size_t)n * HD + c] = __float2half(y);
}

// ---------------- main GEMM (mma.sync, 512 thr, 3-stage, 1 sync/iter) ----------------
// D[128 x 256] = A[128 x K] * WT^T   (WT is [N,K] fp16 row-major)
#define BM 128
#define BN 256
#define BK 32
#define ASTR 40                          // BK + 8 halfs: ldmatrix conflict-free
#define A_BYTES (BM * ASTR * 2)          // 10240 per stage
#define B_BYTES (BN * ASTR * 2)          // 20480 per stage
#define NSTAGE 3
#define SMEM_MMA (NSTAGE * (A_BYTES + B_BYTES))  // 92160
#define SMEM_LN2 (128 * 264 * 4)                 // 135168

#define EPI_GELU 0
#define EPI_LN2  2

// AF32: A operand is fp32 in gmem; convert in the producer path.
template <int K, int EPI, bool AF32>
__global__ void __launch_bounds__(512, 1)
gemm_kernel(const void* __restrict__ Ain, const __half* __restrict__ WT_full,
            const float* __restrict__ bias_full,
            __half* __restrict__ out, int ldout,
            const float* __restrict__ h_res, const float* __restrict__ ln_g,
            const float* __restrict__ ln_b, float* __restrict__ outf) {
    extern __shared__ char smem[];
    __half* As = (__half*)smem;
    const int tid = threadIdx.x;
    const int m0  = blockIdx.x * BM;
    const int n0g = blockIdx.y * BN;
    const __half* WT  = WT_full + (size_t)n0g * K;
    const float* bias = bias_full + n0g;
    const __half* Ah  = (const __half*)Ain;
    const float*  Af  = (const float*)Ain;

    const uint32_t sA = (uint32_t)__cvta_generic_to_shared(smem);
    const uint32_t sB = sA + NSTAGE * A_BYTES;

    const int lane = tid & 31, warp = tid >> 5;
    const int wm = warp & 3, wn = warp >> 2;      // 4 m-warps x 4 n-warps; warp tile 32x64
    const int ml = lane & 7, tl = lane >> 3;

    // producer: A one 16B chunk/thread, B two 16B chunks/thread
    const int pr = tid >> 2, pq = tid & 3;
    auto issue_tile = [&](int kc, int slot) {
        if constexpr (AF32) {
            const float4* p = (const float4*)(Af + (size_t)(m0 + pr) * K + kc * BK + pq * 8);
            float4 v0 = p[0], v1 = p[1];
            alignas(16) __half2 hv[4];
            hv[0] = __floats2half2_rn(v0.x, v0.y);
            hv[1] = __floats2half2_rn(v0.z, v0.w);
            hv[2] = __floats2half2_rn(v1.x, v1.y);
            hv[3] = __floats2half2_rn(v1.z, v1.w);
            *(uint4*)(As + slot * (A_BYTES / 2) + pr * ASTR + pq * 8) = *(uint4*)hv;
        } else {
            cpasync16(sA + slot * A_BYTES + (uint32_t)((pr * ASTR + pq * 8) * 2),
                      Ah + (size_t)(m0 + pr) * K + kc * BK + pq * 8);
        }
#pragma unroll
        for (int i = 0; i < 2; i++) {
            int idx = tid + i * 512;
            int r = idx >> 2, q = idx & 3;
            cpasync16(sB + slot * B_BYTES + (uint32_t)((r * ASTR + q * 8) * 2),
                      WT + (size_t)r * K + kc * BK + q * 8);
        }
        cp_commit();
    };

    float acc[2][8][4];
#pragma unroll
    for (int mi = 0; mi < 2; mi++)
#pragma unroll
        for (int nj = 0; nj < 8; nj++)
#pragma unroll
            for (int j = 0; j < 4; j++) acc[mi][nj][j] = 0.f;

    const int NC = K / BK;
    issue_tile(0, 0);
    issue_tile(1, 1);

    for (int c = 0; c < NC; c++) {
        const int slot = c % NSTAGE;
        if (c + 1 < NC) asm volatile("cp.async.wait_group 1;" ::: "memory");
        else            asm volatile("cp.async.wait_group 0;" ::: "memory");
        __syncthreads();
        if (c + 2 < NC) issue_tile(c + 2, (c + 2) % NSTAGE);

        const uint32_t aB = sA + slot * A_BYTES;
        const uint32_t bB = sB + slot * B_BYTES;
#pragma unroll
        for (int ks = 0; ks < 2; ks++) {
            const int kofs = ks * 16;
            uint32_t afr[2][4];
#pragma unroll
            for (int mi = 0; mi < 2; mi++) {
                int row = wm * 32 + mi * 16 + ml + (tl & 1) * 8;
                int col = kofs + (tl >> 1) * 8;
                ldsm4(afr[mi], aB + (uint32_t)((row * ASTR + col) * 2));
            }
#pragma unroll
            for (int jj = 0; jj < 4; jj++) {
                uint32_t bfr[4];
                int rn  = wn * 64 + jj * 16 + ml + (tl >> 1) * 8;
                int col = kofs + (tl & 1) * 8;
                ldsm4(bfr, bB + (uint32_t)((rn * ASTR + col) * 2));
#pragma unroll
                for (int mi = 0; mi < 2; mi++) {
                    mma16816(acc[mi][2 * jj],     afr[mi], bfr);
                    mma16816(acc[mi][2 * jj + 1], afr[mi], bfr + 2);
                }
            }
        }
    }

    // ---------------- epilogues ----------------
    const int g  = lane >> 2;
    const int t2 = (lane & 3) * 2;

    if constexpr (EPI == EPI_GELU) {
#pragma unroll
        for (int mi = 0; mi < 2; mi++) {
            const int r0 = wm * 32 + mi * 16 + g;
#pragma unroll
            for (int nj = 0; nj < 8; nj++) {
                const int col = wn * 64 + nj * 8 + t2;
                const float b0v = bias[col], b1v = bias[col + 1];
                float x0 = gelu_f(acc[mi][nj][0] + b0v);
                float x1 = gelu_f(acc[mi][nj][1] + b1v);
                *(__half2*)(out + (size_t)(m0 + r0) * ldout + n0g + col) = __floats2half2_rn(x0, x1);
                float x2 = gelu_f(acc[mi][nj][2] + b0v);
                float x3 = gelu_f(acc[mi][nj][3] + b1v);
                *(__half2*)(out + (size_t)(m0 + r0 + 8) * ldout + n0g + col) = __floats2half2_rn(x2, x3);
            }
        }
    } else {  // EPI_LN2: out = LN(h + acc + b2)
        __syncthreads();
        float* sb = (float*)smem;  // [128][264]
#pragma unroll
        for (int mi = 0; mi < 2; mi++) {
            const int r0 = wm * 32 + mi * 16 + g;
#pragma unroll
            for (int nj = 0; nj < 8; nj++) {
                const int col = wn * 64 + nj * 8 + t2;
                const float b0v = bias[col], b1v = bias[col + 1];
                sb[r0 * 264 + col]           = acc[mi][nj][0] + b0v + h_res[(size_t)(m0 + r0) * HD + col];
                sb[r0 * 264 + col + 1]       = acc[mi][nj][1] + b1v + h_res[(size_t)(m0 + r0) * HD + col + 1];
                sb[(r0 + 8) * 264 + col]     = acc[mi][nj][2] + b0v + h_res[(size_t)(m0 + r0 + 8) * HD + col];
                sb[(r0 + 8) * 264 + col + 1] = acc[mi][nj][3] + b1v + h_res[(size_t)(m0 + r0 + 8) * HD + col + 1];
            }
        }
        __syncthreads();
        for (int rr = 0; rr < 8; rr++) {
            const int row = warp * 8 + rr;
            float s = 0.f, s2 = 0.f;
#pragma unroll
            for (int i = 0; i < 8; i++) {
                float v = sb[row * 264 + lane + i * 32];
                s += v; s2 += v * v;
            }
#pragma unroll
            for (int off = 16; off; off >>= 1) {
                s  += __shfl_xor_sync(0xffffffffu, s, off);
                s2 += __shfl_xor_sync(0xffffffffu, s2, off);
            }
            const float mu  = s * (1.0f / HD);
            const float var = s2 * (1.0f / HD) - mu * mu;
            const float rs  = rsqrtf(var + 1e-5f);
#pragma unroll
            for (int i = 0; i < 8; i++) {
                const int cc = lane + i * 32;
                const float v = sb[row * 264 + cc];
                outf[(size_t)(m0 + row) * HD + cc] = (v - mu) * rs * ln_g[cc] + ln_b[cc];
            }
        }
    }
}

// ---------------- host launcher ----------------
extern "C" void kernel_launch(void* const* d_in, const int* in_sizes, int n_in,
                              void* d_out, int out_size) {
    const float* h_V  = (const float*)d_in[0];
    const float* h_E  = (const float*)d_in[1];
    const void*  eidx = d_in[2];
    const float* m0w  = (const float*)d_in[3];
    const float* m0b  = (const float*)d_in[4];
    const float* m1w  = (const float*)d_in[5];
    const float* m1b  = (const float*)d_in[6];
    const float* m2w  = (const float*)d_in[7];
    const float* m2b  = (const float*)d_in[8];
    const float* d0w  = (const float*)d_in[9];
    const float* d0b  = (const float*)d_in[10];
    const float* d1w  = (const float*)d_in[11];
    const float* d1b  = (const float*)d_in[12];
    const float* d2w  = (const float*)d_in[13];
    const float* d2b  = (const float*)d_in[14];
    const float* ln1g = (const float*)d_in[15];
    const float* ln1b = (const float*)d_in[16];
    const float* ln2g = (const float*)d_in[17];
    const float* ln2b = (const float*)d_in[18];
    float* outf = (float*)d_out;
    (void)n_in; (void)out_size; (void)in_sizes;

    void *pWT, *pXa, *pXb, *pH, *pHH;
    cudaGetSymbolAddress(&pWT, g_WT);
    cudaGetSymbolAddress(&pXa, g_Xa);
    cudaGetSymbolAddress(&pXb, g_Xb);
    cudaGetSymbolAddress(&pH,  g_h);
    cudaGetSymbolAddress(&pHH, g_hh);
    __half* WT = (__half*)pWT;
    __half* Xa = (__half*)pXa;
    __half* Xb = (__half*)pXb;
    float*  hb = (float*)pH;
    __half* hh = (__half*)pHH;

    cudaFuncSetAttribute(gemm_kernel<512,  EPI_GELU, true>,  cudaFuncAttributeMaxDynamicSharedMemorySize, SMEM_MMA);
    cudaFuncSetAttribute(gemm_kernel<256,  EPI_GELU, false>, cudaFuncAttributeMaxDynamicSharedMemorySize, SMEM_MMA);
    cudaFuncSetAttribute(gemm_kernel<1024, EPI_GELU, false>, cudaFuncAttributeMaxDynamicSharedMemorySize, SMEM_MMA);
    cudaFuncSetAttribute(gemm_kernel<1024, EPI_LN2,  false>, cudaFuncAttributeMaxDynamicSharedMemorySize, SMEM_LN2);

    // --- prep ---
    detect_idx_kernel<<<1, 32>>>((const int*)eidx);
    prep_wt_kernel<<<(512  * 256  + 255) / 256, 256>>>(m0w, WT + WOFF_M0, 512,  256);
    prep_wt_kernel<<<(256  * 256  + 255) / 256, 256>>>(m1w, WT + WOFF_M1, 256,  256);
    prep_wt_kernel<<<(256  * 256  + 255) / 256, 256>>>(m2w, WT + WOFF_M2, 256,  256);
    prep_wt_kernel<<<(256  * 1024 + 255) / 256, 256>>>(d0w, WT + WOFF_D0, 256,  1024);
    prep_wt_kernel<<<(1024 * 1024 + 255) / 256, 256>>>(d1w, WT + WOFF_D1, 1024, 1024);
    prep_wt_kernel<<<(1024 * 256  + 255) / 256, 256>>>(d2w, WT + WOFF_D2, 1024, 256);

    // --- CSR build ---
    zero_cnt_kernel<<<NNODES / 256, 256>>>();
    count_kernel<<<EDGES / 256, 256>>>(eidx);
    scan_kernel<<<1, 1024>>>();
    fill_kernel<<<EDGES / 256, 256>>>(eidx);

    // --- edge MLP (GEMM1 consumes fp32 h_E directly) ---
    gemm_kernel<512, EPI_GELU, true><<<dim3(EDGES / BM, 1), 512, SMEM_MMA>>>(
        h_E, WT + WOFF_M0, m0b, Xa, HD, nullptr, nullptr, nullptr, nullptr);
    gemm_kernel<256, EPI_GELU, false><<<dim3(EDGES / BM, 1), 512, SMEM_MMA>>>(
        Xa, WT + WOFF_M1, m1b, Xb, HD, nullptr, nullptr, nullptr, nullptr);
    gemm_kernel<256, EPI_GELU, false><<<dim3(EDGES / BM, 1), 512, SMEM_MMA>>>(
        Xb, WT + WOFF_M2, m2b, Xa, HD, nullptr, nullptr, nullptr, nullptr);

    // --- scatter-sum via CSR gather, fused with LN1 ---
    gather_ln1_kernel<<<NNODES, 256>>>(Xa, h_V, ln1g, ln1b, hb, hh);

    // --- dense MLP ---
    gemm_kernel<256, EPI_GELU, false><<<dim3(NNODES / BM, 4), 512, SMEM_MMA>>>(
        hh, WT + WOFF_D0, d0b, Xb, DD, nullptr, nullptr, nullptr, nullptr);
    gemm_kernel<1024, EPI_GELU, false><<<dim3(NNODES / BM, 4), 512, SMEM_MMA>>>(
        Xb, WT + WOFF_D1, d1b, Xa, DD, nullptr, nullptr, nullptr, nullptr);
    gemm_kernel<1024, EPI_LN2, false><<<dim3(NNODES / BM, 1), 512, SMEM_LN2>>>(
        Xa, WT + WOFF_D2, d2b, nullptr, 0, hb, ln2g, ln2b, outf);
}

// round 6
// speedup vs baseline: 1.2046x; 1.0261x over previous
#include <cuda_runtime.h>
#include <cuda_fp16.h>
#include <stdint.h>

// ---------------- problem constants ----------------
#define EDGES   524288
#define NNODES  16384
#define HD      256
#define EIN     512
#define DD      1024

// ---------------- device scratch (no allocations allowed) ----------------
static __device__ int    g_idx64;
static __device__ __half g_WT[1835008];                   // all weights, [N][K] fp16
static __device__ __half g_Xa[(size_t)EDGES * HD];
static __device__ __half g_Xb[(size_t)EDGES * HD];
static __device__ float  g_h [(size_t)NNODES * HD];       // post-LN1 h (fp32 residual)
static __device__ __half g_hh[(size_t)NNODES * HD];       // post-LN1 h (fp16)
// CSR structures
static __device__ int    g_cnt[NNODES];
static __device__ int    g_off[NNODES + 1];
static __device__ int    g_cur[NNODES];
static __device__ int    g_elist[EDGES];

#define WOFF_M0 0         // [256][512]
#define WOFF_M1 131072    // [256][256]
#define WOFF_M2 196608    // [256][256]
#define WOFF_D0 262144    // [1024][256]
#define WOFF_D1 524288    // [1024][1024]
#define WOFF_D2 1572864   // [256][1024]

// ---------------- helpers ----------------
__device__ __forceinline__ float gelu_f(float x) {
    return 0.5f * x * (1.0f + erff(x * 0.70710678118654752f));
}
__device__ __forceinline__ void cpasync16(uint32_t dst, const void* src) {
    asm volatile("cp.async.cg.shared.global [%0], [%1], 16;" :: "r"(dst), "l"(src) : "memory");
}
__device__ __forceinline__ void cp_commit() {
    asm volatile("cp.async.commit_group;" ::: "memory");
}
__device__ __forceinline__ void ldsm4(uint32_t* r, uint32_t addr) {
    asm volatile("ldmatrix.sync.aligned.m8n8.x4.shared.b16 {%0,%1,%2,%3}, [%4];"
                 : "=r"(r[0]), "=r"(r[1]), "=r"(r[2]), "=r"(r[3]) : "r"(addr));
}
__device__ __forceinline__ void mma16816(float* c, const uint32_t* a, const uint32_t* b) {
    asm volatile("mma.sync.aligned.m16n8k16.row.col.f32.f16.f16.f32 "
                 "{%0,%1,%2,%3}, {%4,%5,%6,%7}, {%8,%9}, {%0,%1,%2,%3};"
                 : "+f"(c[0]), "+f"(c[1]), "+f"(c[2]), "+f"(c[3])
                 : "r"(a[0]), "r"(a[1]), "r"(a[2]), "r"(a[3]), "r"(b[0]), "r"(b[1]));
}

// ---------------- prep kernels ----------------
__global__ void detect_idx_kernel(const int* p) {
    if (threadIdx.x == 0 && blockIdx.x == 0) {
        int is64 = 1;
        for (int i = 1; i < 512; i += 2)
            if (p[i] != 0) { is64 = 0; break; }
        g_idx64 = is64;
    }
}

// W [K,N] fp32 row-major -> WT [N,K] fp16 row-major
__global__ void prep_wt_kernel(const float* __restrict__ W, __half* __restrict__ WT, int K, int N) {
    long long idx = (long long)blockIdx.x * blockDim.x + threadIdx.x;
    if (idx >= (long long)K * N) return;
    int k = (int)(idx / N);
    int n = (int)(idx % N);
    WT[(long long)n * K + k] = __float2half(W[idx]);
}

// ---------------- CSR build ----------------
__global__ void zero_cnt_kernel() {
    int i = blockIdx.x * 256 + threadIdx.x;
    if (i < NNODES) g_cnt[i] = 0;
}
__global__ void count_kernel(const void* __restrict__ eidx) {
    int e = blockIdx.x * 256 + threadIdx.x;
    int n = g_idx64 ? (int)((const long long*)eidx)[e] : ((const int*)eidx)[e];
    atomicAdd(&g_cnt[n], 1);
}
__global__ void scan_kernel() {
    __shared__ int part[1024];
    int t = threadIdx.x;
    int loc[16]; int s = 0;
#pragma unroll
    for (int i = 0; i < 16; i++) { loc[i] = g_cnt[t * 16 + i]; s += loc[i]; }
    part[t] = s;
    __syncthreads();
    for (int o = 1; o < 1024; o <<= 1) {
        int v = (t >= o) ? part[t - o] : 0;
        __syncthreads();
        part[t] += v;
        __syncthreads();
    }
    int run = (t == 0) ? 0 : part[t - 1];
#pragma unroll
    for (int i = 0; i < 16; i++) { g_off[t * 16 + i] = run; g_cur[t * 16 + i] = run; run += loc[i]; }
    if (t == 1023) g_off[NNODES] = run;
}
__global__ void fill_kernel(const void* __restrict__ eidx) {
    int e = blockIdx.x * 256 + threadIdx.x;
    int n = g_idx64 ? (int)((const long long*)eidx)[e] : ((const int*)eidx)[e];
    int pos = atomicAdd(&g_cur[n], 1);
    g_elist[pos] = e;
}

// ---------------- fused gather + LN1 ----------------
__global__ void gather_ln1_kernel(const __half* __restrict__ m,
                                  const float* __restrict__ hV,
                                  const float* __restrict__ g1, const float* __restrict__ b1,
                                  float* __restrict__ h, __half* __restrict__ hh) {
    __shared__ float sm1[8], sm2[8];
    const int n = blockIdx.x, c = threadIdx.x;
    const int wid = c >> 5, lane = c & 31;
    const int s = g_off[n], e = g_off[n + 1];
    float acc = 0.f;
    int i = s;
    for (; i + 4 <= e; i += 4) {
        int e0 = g_elist[i], e1 = g_elist[i + 1], e2 = g_elist[i + 2], e3 = g_elist[i + 3];
        acc += __half2float(m[(size_t)e0 * HD + c]);
        acc += __half2float(m[(size_t)e1 * HD + c]);
        acc += __half2float(m[(size_t)e2 * HD + c]);
        acc += __half2float(m[(size_t)e3 * HD + c]);
    }
    for (; i < e; i++)
        acc += __half2float(m[(size_t)g_elist[i] * HD + c]);

    const float v = hV[(size_t)n * HD + c] + acc * (1.0f / 30.0f);
    float s1 = v, s2 = v * v;
#pragma unroll
    for (int off = 16; off; off >>= 1) {
        s1 += __shfl_xor_sync(0xffffffffu, s1, off);
        s2 += __shfl_xor_sync(0xffffffffu, s2, off);
    }
    if (lane == 0) { sm1[wid] = s1; sm2[wid] = s2; }
    __syncthreads();
    float t1 = 0.f, t2 = 0.f;
#pragma unroll
    for (int k = 0; k < 8; k++) { t1 += sm1[k]; t2 += sm2[k]; }
    const float mu  = t1 * (1.0f / HD);
    const float var = t2 * (1.0f / HD) - mu * mu;
    const float rs  = rsqrtf(var + 1e-5f);
    const float y = (v - mu) * rs * g1[c] + b1[c];
    h [(size_t)n * HD + c] = y;
    hh[(size_t)n * HD + c] = __float2half(y);
}

// ---------------- main GEMM (mma.sync, 512 thr, BK=64, 3-stage, 1 sync/iter) ----------------
// D[128 x 256] = A[128 x K] * WT^T   (WT is [N,K] fp16 row-major)
#define BM 128
#define BN 256
#define BK 64
#define ASTR 72                          // BK + 8 halfs: ldmatrix conflict-free
#define A_BYTES (BM * ASTR * 2)          // 18432 per stage
#define B_BYTES (BN * ASTR * 2)          // 36864 per stage
#define NSTAGE 3
#define SMEM_MMA (NSTAGE * (A_BYTES + B_BYTES))  // 165888 (also covers LN2's 135168 float buf)

#define EPI_GELU 0
#define EPI_LN2  2

// AF32: A operand is fp32 in gmem; LDG->regs prefetched one iter ahead, STS as fp16.
template <int K, int EPI, bool AF32>
__global__ void __launch_bounds__(512, 1)
gemm_kernel(const void* __restrict__ Ain, const __half* __restrict__ WT_full,
            const float* __restrict__ bias_full,
            __half* __restrict__ out, int ldout,
            const float* __restrict__ h_res, const float* __restrict__ ln_g,
            const float* __restrict__ ln_b, float* __restrict__ outf) {
    extern __shared__ char smem[];
    __half* As = (__half*)smem;
    const int tid = threadIdx.x;
    const int m0  = blockIdx.x * BM;
    const int n0g = blockIdx.y * BN;
    const __half* WT  = WT_full + (size_t)n0g * K;
    const float* bias = bias_full + n0g;
    const __half* Ah  = (const __half*)Ain;
    const float*  Af  = (const float*)Ain;

    const uint32_t sA = (uint32_t)__cvta_generic_to_shared(smem);
    const uint32_t sB = sA + NSTAGE * A_BYTES;

    const int lane = tid & 31, warp = tid >> 5;
    const int wm = warp & 3, wn = warp >> 2;      // 4 m-warps x 4 n-warps; warp tile 32x64
    const int ml = lane & 7, tl = lane >> 3;

    // A: 1024 16B-chunks/stage -> 2 per thread. B: 2048 -> 4 per thread.
    // chunk idx -> row = idx>>3, quad = idx&7 (8 chunks per 128B row)
    float4 ra[2][2];  // AF32 prefetch registers: 2 chunks x 8 floats
    auto ldgA = [&](int kc) {
        if constexpr (AF32) {
#pragma unroll
            for (int i = 0; i < 2; i++) {
                int idx = tid + i * 512;
                int r = idx >> 3, q = idx & 7;
                const float4* p = (const float4*)(Af + (size_t)(m0 + r) * K + kc * BK + q * 8);
                ra[i][0] = p[0];
                ra[i][1] = p[1];
            }
        }
    };
    auto stsA = [&](int slot) {
        if constexpr (AF32) {
#pragma unroll
            for (int i = 0; i < 2; i++) {
                int idx = tid + i * 512;
                int r = idx >> 3, q = idx & 7;
                alignas(16) __half2 hv[4];
                hv[0] = __floats2half2_rn(ra[i][0].x, ra[i][0].y);
                hv[1] = __floats2half2_rn(ra[i][0].z, ra[i][0].w);
                hv[2] = __floats2half2_rn(ra[i][1].x, ra[i][1].y);
                hv[3] = __floats2half2_rn(ra[i][1].z, ra[i][1].w);
                *(uint4*)(As + slot * (A_BYTES / 2) + r * ASTR + q * 8) = *(uint4*)hv;
            }
        }
    };
    auto issueB = [&](int kc, int slot) {
        if constexpr (!AF32) {
#pragma unroll
            for (int i = 0; i < 2; i++) {
                int idx = tid + i * 512;
                int r = idx >> 3, q = idx & 7;
                cpasync16(sA + slot * A_BYTES + (uint32_t)((r * ASTR + q * 8) * 2),
                          Ah + (size_t)(m0 + r) * K + kc * BK + q * 8);
            }
        }
#pragma unroll
        for (int i = 0; i < 4; i++) {
            int idx = tid + i * 512;
            int r = idx >> 3, q = idx & 7;
            cpasync16(sB + slot * B_BYTES + (uint32_t)((r * ASTR + q * 8) * 2),
                      WT + (size_t)r * K + kc * BK + q * 8);
        }
        cp_commit();
    };

    float acc[2][8][4];
#pragma unroll
    for (int mi = 0; mi < 2; mi++)
#pragma unroll
        for (int nj = 0; nj < 8; nj++)
#pragma unroll
            for (int j = 0; j < 4; j++) acc[mi][nj][j] = 0.f;

    const int NC = K / BK;   // >= 4 for all instantiations
    // prologue: fill stages 0,1; prefetch regs for chunk 2
    ldgA(0); stsA(0); issueB(0, 0);
    ldgA(1); stsA(1); issueB(1, 1);
    ldgA(2);

    for (int c = 0; c < NC; c++) {
        const int slot = c % NSTAGE;
        if (c + 1 < NC) asm volatile("cp.async.wait_group 1;" ::: "memory");
        else            asm volatile("cp.async.wait_group 0;" ::: "memory");
        __syncthreads();
        if (c + 2 < NC) {
            stsA((c + 2) % NSTAGE);      // regs loaded at iter c-1 (or prologue)
            issueB(c + 2, (c + 2) % NSTAGE);
            if (c + 3 < NC) ldgA(c + 3); // hidden under this iter's mma
        }

        const uint32_t aB = sA + slot * A_BYTES;
        const uint32_t bB = sB + slot * B_BYTES;
#pragma unroll
        for (int ks = 0; ks < 4; ks++) {
            const int kofs = ks * 16;
            uint32_t afr[2][4];
#pragma unroll
            for (int mi = 0; mi < 2; mi++) {
                int row = wm * 32 + mi * 16 + ml + (tl & 1) * 8;
                int col = kofs + (tl >> 1) * 8;
                ldsm4(afr[mi], aB + (uint32_t)((row * ASTR + col) * 2));
            }
#pragma unroll
            for (int jj = 0; jj < 4; jj++) {
                uint32_t bfr[4];
                int rn  = wn * 64 + jj * 16 + ml + (tl >> 1) * 8;
                int col = kofs + (tl & 1) * 8;
                ldsm4(bfr, bB + (uint32_t)((rn * ASTR + col) * 2));
#pragma unroll
                for (int mi = 0; mi < 2; mi++) {
                    mma16816(acc[mi][2 * jj],     afr[mi], bfr);
                    mma16816(acc[mi][2 * jj + 1], afr[mi], bfr + 2);
                }
            }
        }
    }

    // ---------------- epilogues ----------------
    const int g  = lane >> 2;
    const int t2 = (lane & 3) * 2;

    if constexpr (EPI == EPI_GELU) {
#pragma unroll
        for (int mi = 0; mi < 2; mi++) {
            const int r0 = wm * 32 + mi * 16 + g;
#pragma unroll
            for (int nj = 0; nj < 8; nj++) {
                const int col = wn * 64 + nj * 8 + t2;
                const float b0v = bias[col], b1v = bias[col + 1];
                float x0 = gelu_f(acc[mi][nj][0] + b0v);
                float x1 = gelu_f(acc[mi][nj][1] + b1v);
                *(__half2*)(out + (size_t)(m0 + r0) * ldout + n0g + col) = __floats2half2_rn(x0, x1);
                float x2 = gelu_f(acc[mi][nj][2] + b0v);
                float x3 = gelu_f(acc[mi][nj][3] + b1v);
                *(__half2*)(out + (size_t)(m0 + r0 + 8) * ldout + n0g + col) = __floats2half2_rn(x2, x3);
            }
        }
    } else {  // EPI_LN2: out = LN(h + acc + b2)
        __syncthreads();
        float* sb = (float*)smem;  // [128][264] floats (135168 B <= SMEM_MMA)
#pragma unroll
        for (int mi = 0; mi < 2; mi++) {
            const int r0 = wm * 32 + mi * 16 + g;
#pragma unroll
            for (int nj = 0; nj < 8; nj++) {
                const int col = wn * 64 + nj * 8 + t2;
                const float b0v = bias[col], b1v = bias[col + 1];
                sb[r0 * 264 + col]           = acc[mi][nj][0] + b0v + h_res[(size_t)(m0 + r0) * HD + col];
                sb[r0 * 264 + col + 1]       = acc[mi][nj][1] + b1v + h_res[(size_t)(m0 + r0) * HD + col + 1];
                sb[(r0 + 8) * 264 + col]     = acc[mi][nj][2] + b0v + h_res[(size_t)(m0 + r0 + 8) * HD + col];
                sb[(r0 + 8) * 264 + col + 1] = acc[mi][nj][3] + b1v + h_res[(size_t)(m0 + r0 + 8) * HD + col + 1];
            }
        }
        __syncthreads();
        for (int rr = 0; rr < 8; rr++) {
            const int row = warp * 8 + rr;
            float s = 0.f, s2 = 0.f;
#pragma unroll
            for (int i = 0; i < 8; i++) {
                float v = sb[row * 264 + lane + i * 32];
                s += v; s2 += v * v;
            }
#pragma unroll
            for (int off = 16; off; off >>= 1) {
                s  += __shfl_xor_sync(0xffffffffu, s, off);
                s2 += __shfl_xor_sync(0xffffffffu, s2, off);
            }
            const float mu  = s * (1.0f / HD);
            const float var = s2 * (1.0f / HD) - mu * mu;
            const float rs  = rsqrtf(var + 1e-5f);
#pragma unroll
            for (int i = 0; i < 8; i++) {
                const int cc = lane + i * 32;
                const float v = sb[row * 264 + cc];
                outf[(size_t)(m0 + row) * HD + cc] = (v - mu) * rs * ln_g[cc] + ln_b[cc];
            }
        }
    }
}

// ---------------- host launcher ----------------
extern "C" void kernel_launch(void* const* d_in, const int* in_sizes, int n_in,
                              void* d_out, int out_size) {
    const float* h_V  = (const float*)d_in[0];
    const float* h_E  = (const float*)d_in[1];
    const void*  eidx = d_in[2];
    const float* m0w  = (const float*)d_in[3];
    const float* m0b  = (const float*)d_in[4];
    const float* m1w  = (const float*)d_in[5];
    const float* m1b  = (const float*)d_in[6];
    const float* m2w  = (const float*)d_in[7];
    const float* m2b  = (const float*)d_in[8];
    const float* d0w  = (const float*)d_in[9];
    const float* d0b  = (const float*)d_in[10];
    const float* d1w  = (const float*)d_in[11];
    const float* d1b  = (const float*)d_in[12];
    const float* d2w  = (const float*)d_in[13];
    const float* d2b  = (const float*)d_in[14];
    const float* ln1g = (const float*)d_in[15];
    const float* ln1b = (const float*)d_in[16];
    const float* ln2g = (const float*)d_in[17];
    const float* ln2b = (const float*)d_in[18];
    float* outf = (float*)d_out;
    (void)n_in; (void)out_size; (void)in_sizes;

    void *pWT, *pXa, *pXb, *pH, *pHH;
    cudaGetSymbolAddress(&pWT, g_WT);
    cudaGetSymbolAddress(&pXa, g_Xa);
    cudaGetSymbolAddress(&pXb, g_Xb);
    cudaGetSymbolAddress(&pH,  g_h);
    cudaGetSymbolAddress(&pHH, g_hh);
    __half* WT = (__half*)pWT;
    __half* Xa = (__half*)pXa;
    __half* Xb = (__half*)pXb;
    float*  hb = (float*)pH;
    __half* hh = (__half*)pHH;

    cudaFuncSetAttribute(gemm_kernel<512,  EPI_GELU, true>,  cudaFuncAttributeMaxDynamicSharedMemorySize, SMEM_MMA);
    cudaFuncSetAttribute(gemm_kernel<256,  EPI_GELU, false>, cudaFuncAttributeMaxDynamicSharedMemorySize, SMEM_MMA);
    cudaFuncSetAttribute(gemm_kernel<1024, EPI_GELU, false>, cudaFuncAttributeMaxDynamicSharedMemorySize, SMEM_MMA);
    cudaFuncSetAttribute(gemm_kernel<1024, EPI_LN2,  false>, cudaFuncAttributeMaxDynamicSharedMemorySize, SMEM_MMA);

    // --- launch order arranged so GEMM1 is the 6th launch (ncu -s 5 -c 1 captures it) ---
    detect_idx_kernel<<<1, 32>>>((const int*)eidx);                              // 0
    prep_wt_kernel<<<(512 * 256 + 255) / 256, 256>>>(m0w, WT + WOFF_M0, 512, 256); // 1
    zero_cnt_kernel<<<NNODES / 256, 256>>>();                                    // 2
    count_kernel<<<EDGES / 256, 256>>>(eidx);                                    // 3
    scan_kernel<<<1, 1024>>>();                                                  // 4

    // GEMM1 (consumes fp32 h_E directly, converts in-flight)                    // 5 <- profiled
    gemm_kernel<512, EPI_GELU, true><<<dim3(EDGES / BM, 1), 512, SMEM_MMA>>>(
        h_E, WT + WOFF_M0, m0b, Xa, HD, nullptr, nullptr, nullptr, nullptr);

    fill_kernel<<<EDGES / 256, 256>>>(eidx);
    prep_wt_kernel<<<(256  * 256  + 255) / 256, 256>>>(m1w, WT + WOFF_M1, 256,  256);
    prep_wt_kernel<<<(256  * 256  + 255) / 256, 256>>>(m2w, WT + WOFF_M2, 256,  256);
    prep_wt_kernel<<<(256  * 1024 + 255) / 256, 256>>>(d0w, WT + WOFF_D0, 256,  1024);
    prep_wt_kernel<<<(1024 * 1024 + 255) / 256, 256>>>(d1w, WT + WOFF_D1, 1024, 1024);
    prep_wt_kernel<<<(1024 * 256  + 255) / 256, 256>>>(d2w, WT + WOFF_D2, 1024, 256);

    // --- edge MLP layers 2,3 ---
    gemm_kernel<256, EPI_GELU, false><<<dim3(EDGES / BM, 1), 512, SMEM_MMA>>>(
        Xa, WT + WOFF_M1, m1b, Xb, HD, nullptr, nullptr, nullptr, nullptr);
    gemm_kernel<256, EPI_GELU, false><<<dim3(EDGES / BM, 1), 512, SMEM_MMA>>>(
        Xb, WT + WOFF_M2, m2b, Xa, HD, nullptr, nullptr, nullptr, nullptr);

    // --- scatter-sum via CSR gather, fused with LN1 ---
    gather_ln1_kernel<<<NNODES, 256>>>(Xa, h_V, ln1g, ln1b, hb, hh);

    // --- dense MLP ---
    gemm_kernel<256, EPI_GELU, false><<<dim3(NNODES / BM, 4), 512, SMEM_MMA>>>(
        hh, WT + WOFF_D0, d0b, Xb, DD, nullptr, nullptr, nullptr, nullptr);
    gemm_kernel<1024, EPI_GELU, false><<<dim3(NNODES / BM, 4), 512, SMEM_MMA>>>(
        Xb, WT + WOFF_D1, d1b, Xa, DD, nullptr, nullptr, nullptr, nullptr);
    gemm_kernel<1024, EPI_LN2, false><<<dim3(NNODES / BM, 1), 512, SMEM_MMA>>>(
        Xa, WT + WOFF_D2, d2b, nullptr, 0, hb, ln2g, ln2b, outf);
}

// round 7
// speedup vs baseline: 1.2586x; 1.0448x over previous
#include <cuda_runtime.h>
#include <cuda_fp16.h>
#include <stdint.h>

// ---------------- problem constants ----------------
#define EDGES   524288
#define NNODES  16384
#define HD      256
#define EIN     512
#define DD      1024

// ---------------- device scratch (no allocations allowed) ----------------
static __device__ int    g_idx64;
static __device__ __half g_WT[1835008];                   // all weights, [N][K] fp16
static __device__ __half g_Xa[(size_t)EDGES * HD];
static __device__ __half g_Xb[(size_t)EDGES * HD];
static __device__ float  g_h [(size_t)NNODES * HD];       // post-LN1 h (fp32 residual)
static __device__ __half g_hh[(size_t)NNODES * HD];       // post-LN1 h (fp16)
// CSR structures
static __device__ int    g_cnt[NNODES];
static __device__ int    g_off[NNODES + 1];
static __device__ int    g_cur[NNODES];
static __device__ int    g_elist[EDGES];

#define WOFF_M0 0         // [256][512]
#define WOFF_M1 131072    // [256][256]
#define WOFF_M2 196608    // [256][256]
#define WOFF_D0 262144    // [1024][256]
#define WOFF_D1 524288    // [1024][1024]
#define WOFF_D2 1572864   // [256][1024]

// ---------------- helpers ----------------
__device__ __forceinline__ float gelu_f(float x) {
    return 0.5f * x * (1.0f + erff(x * 0.70710678118654752f));
}
__device__ __forceinline__ void cpasync16(uint32_t dst, const void* src) {
    asm volatile("cp.async.cg.shared.global [%0], [%1], 16;" :: "r"(dst), "l"(src) : "memory");
}
__device__ __forceinline__ void cp_commit() {
    asm volatile("cp.async.commit_group;" ::: "memory");
}
__device__ __forceinline__ void ldsm4(uint32_t* r, uint32_t addr) {
    asm volatile("ldmatrix.sync.aligned.m8n8.x4.shared.b16 {%0,%1,%2,%3}, [%4];"
                 : "=r"(r[0]), "=r"(r[1]), "=r"(r[2]), "=r"(r[3]) : "r"(addr));
}
__device__ __forceinline__ void mma16816(float* c, const uint32_t* a, const uint32_t* b) {
    asm volatile("mma.sync.aligned.m16n8k16.row.col.f32.f16.f16.f32 "
                 "{%0,%1,%2,%3}, {%4,%5,%6,%7}, {%8,%9}, {%0,%1,%2,%3};"
                 : "+f"(c[0]), "+f"(c[1]), "+f"(c[2]), "+f"(c[3])
                 : "r"(a[0]), "r"(a[1]), "r"(a[2]), "r"(a[3]), "r"(b[0]), "r"(b[1]));
}

// ---------------- prep kernels ----------------
__global__ void detect_idx_kernel(const int* p) {
    if (threadIdx.x == 0 && blockIdx.x == 0) {
        int is64 = 1;
        for (int i = 1; i < 512; i += 2)
            if (p[i] != 0) { is64 = 0; break; }
        g_idx64 = is64;
    }
}

// W [K,N] fp32 row-major -> WT [N,K] fp16 row-major
__global__ void prep_wt_kernel(const float* __restrict__ W, __half* __restrict__ WT, int K, int N) {
    long long idx = (long long)blockIdx.x * blockDim.x + threadIdx.x;
    if (idx >= (long long)K * N) return;
    int k = (int)(idx / N);
    int n = (int)(idx % N);
    WT[(long long)n * K + k] = __float2half(W[idx]);
}

// ---------------- CSR build ----------------
__global__ void zero_cnt_kernel() {
    int i = blockIdx.x * 256 + threadIdx.x;
    if (i < NNODES) g_cnt[i] = 0;
}
__global__ void count_kernel(const void* __restrict__ eidx) {
    int e = blockIdx.x * 256 + threadIdx.x;
    int n = g_idx64 ? (int)((const long long*)eidx)[e] : ((const int*)eidx)[e];
    atomicAdd(&g_cnt[n], 1);
}
__global__ void scan_kernel() {
    __shared__ int part[1024];
    int t = threadIdx.x;
    int loc[16]; int s = 0;
#pragma unroll
    for (int i = 0; i < 16; i++) { loc[i] = g_cnt[t * 16 + i]; s += loc[i]; }
    part[t] = s;
    __syncthreads();
    for (int o = 1; o < 1024; o <<= 1) {
        int v = (t >= o) ? part[t - o] : 0;
        __syncthreads();
        part[t] += v;
        __syncthreads();
    }
    int run = (t == 0) ? 0 : part[t - 1];
#pragma unroll
    for (int i = 0; i < 16; i++) { g_off[t * 16 + i] = run; g_cur[t * 16 + i] = run; run += loc[i]; }
    if (t == 1023) g_off[NNODES] = run;
}
__global__ void fill_kernel(const void* __restrict__ eidx) {
    int e = blockIdx.x * 256 + threadIdx.x;
    int n = g_idx64 ? (int)((const long long*)eidx)[e] : ((const int*)eidx)[e];
    int pos = atomicAdd(&g_cur[n], 1);
    g_elist[pos] = e;
}

// ---------------- fused gather + LN1 ----------------
__global__ void gather_ln1_kernel(const __half* __restrict__ m,
                                  const float* __restrict__ hV,
                                  const float* __restrict__ g1, const float* __restrict__ b1,
                                  float* __restrict__ h, __half* __restrict__ hh) {
    __shared__ float sm1[8], sm2[8];
    const int n = blockIdx.x, c = threadIdx.x;
    const int wid = c >> 5, lane = c & 31;
    const int s = g_off[n], e = g_off[n + 1];
    float acc = 0.f;
    int i = s;
    for (; i + 4 <= e; i += 4) {
        int e0 = g_elist[i], e1 = g_elist[i + 1], e2 = g_elist[i + 2], e3 = g_elist[i + 3];
        acc += __half2float(m[(size_t)e0 * HD + c]);
        acc += __half2float(m[(size_t)e1 * HD + c]);
        acc += __half2float(m[(size_t)e2 * HD + c]);
        acc += __half2float(m[(size_t)e3 * HD + c]);
    }
    for (; i < e; i++)
        acc += __half2float(m[(size_t)g_elist[i] * HD + c]);

    const float v = hV[(size_t)n * HD + c] + acc * (1.0f / 30.0f);
    float s1 = v, s2 = v * v;
#pragma unroll
    for (int off = 16; off; off >>= 1) {
        s1 += __shfl_xor_sync(0xffffffffu, s1, off);
        s2 += __shfl_xor_sync(0xffffffffu, s2, off);
    }
    if (lane == 0) { sm1[wid] = s1; sm2[wid] = s2; }
    __syncthreads();
    float t1 = 0.f, t2 = 0.f;
#pragma unroll
    for (int k = 0; k < 8; k++) { t1 += sm1[k]; t2 += sm2[k]; }
    const float mu  = t1 * (1.0f / HD);
    const float var = t2 * (1.0f / HD) - mu * mu;
    const float rs  = rsqrtf(var + 1e-5f);
    const float y = (v - mu) * rs * g1[c] + b1[c];
    h [(size_t)n * HD + c] = y;
    hh[(size_t)n * HD + c] = __float2half(y);
}

// ---------------- GEMM tiling constants ----------------
#define BM 128
#define BN 256
#define BK 64
#define ASTR 72                          // BK + 8 halfs: ldmatrix conflict-free
#define A_BYTES (BM * ASTR * 2)          // 18432 per stage
#define B_BYTES (BN * ASTR * 2)          // 36864 per stage
#define NSTAGE 3
#define SMEM_MMA (NSTAGE * (A_BYTES + B_BYTES))  // 165888
// fused kernel layout: A2 (4 chunks) overlays stage-1 slots after mainloop1
#define A2_OFF  0                        // 4 * A_BYTES = 73728
#define B2_OFF  (4 * A_BYTES)            // two B stages: 73728 .. 147456

#define EPI_GELU 0
#define EPI_LN2  2

// ---------------- main GEMM (mma.sync, 512 thr, BK=64, 3-stage) ----------------
// AF32: A operand is fp32 in gmem; LDG->regs prefetched one iter ahead, STS as fp16.
template <int K, int EPI, bool AF32>
__global__ void __launch_bounds__(512, 1)
gemm_kernel(const void* __restrict__ Ain, const __half* __restrict__ WT_full,
            const float* __restrict__ bias_full,
            __half* __restrict__ out, int ldout,
            const float* __restrict__ h_res, const float* __restrict__ ln_g,
            const float* __restrict__ ln_b, float* __restrict__ outf) {
    extern __shared__ char smem[];
    __half* As = (__half*)smem;
    const int tid = threadIdx.x;
    const int m0  = blockIdx.x * BM;
    const int n0g = blockIdx.y * BN;
    const __half* WT  = WT_full + (size_t)n0g * K;
    const float* bias = bias_full + n0g;
    const __half* Ah  = (const __half*)Ain;
    const float*  Af  = (const float*)Ain;

    const uint32_t sA = (uint32_t)__cvta_generic_to_shared(smem);
    const uint32_t sB = sA + NSTAGE * A_BYTES;

    const int lane = tid & 31, warp = tid >> 5;
    const int wm = warp & 3, wn = warp >> 2;      // 4 m-warps x 4 n-warps; warp tile 32x64
    const int ml = lane & 7, tl = lane >> 3;

    float4 ra[2][2];
    auto ldgA = [&](int kc) {
        if constexpr (AF32) {
#pragma unroll
            for (int i = 0; i < 2; i++) {
                int idx = tid + i * 512;
                int r = idx >> 3, q = idx & 7;
                const float4* p = (const float4*)(Af + (size_t)(m0 + r) * K + kc * BK + q * 8);
                ra[i][0] = p[0];
                ra[i][1] = p[1];
            }
        }
    };
    auto stsA = [&](int slot) {
        if constexpr (AF32) {
#pragma unroll
            for (int i = 0; i < 2; i++) {
                int idx = tid + i * 512;
                int r = idx >> 3, q = idx & 7;
                alignas(16) __half2 hv[4];
                hv[0] = __floats2half2_rn(ra[i][0].x, ra[i][0].y);
                hv[1] = __floats2half2_rn(ra[i][0].z, ra[i][0].w);
                hv[2] = __floats2half2_rn(ra[i][1].x, ra[i][1].y);
                hv[3] = __floats2half2_rn(ra[i][1].z, ra[i][1].w);
                *(uint4*)(As + slot * (A_BYTES / 2) + r * ASTR + q * 8) = *(uint4*)hv;
            }
        }
    };
    auto issueB = [&](int kc, int slot) {
        if constexpr (!AF32) {
#pragma unroll
            for (int i = 0; i < 2; i++) {
                int idx = tid + i * 512;
                int r = idx >> 3, q = idx & 7;
                cpasync16(sA + slot * A_BYTES + (uint32_t)((r * ASTR + q * 8) * 2),
                          Ah + (size_t)(m0 + r) * K + kc * BK + q * 8);
            }
        }
#pragma unroll
        for (int i = 0; i < 4; i++) {
            int idx = tid + i * 512;
            int r = idx >> 3, q = idx & 7;
            cpasync16(sB + slot * B_BYTES + (uint32_t)((r * ASTR + q * 8) * 2),
                      WT + (size_t)r * K + kc * BK + q * 8);
        }
        cp_commit();
    };

    float acc[2][8][4];
#pragma unroll
    for (int mi = 0; mi < 2; mi++)
#pragma unroll
        for (int nj = 0; nj < 8; nj++)
#pragma unroll
            for (int j = 0; j < 4; j++) acc[mi][nj][j] = 0.f;

    const int NC = K / BK;
    ldgA(0); stsA(0); issueB(0, 0);
    ldgA(1); stsA(1); issueB(1, 1);
    ldgA(2);

    for (int c = 0; c < NC; c++) {
        const int slot = c % NSTAGE;
        if (c + 1 < NC) asm volatile("cp.async.wait_group 1;" ::: "memory");
        else            asm volatile("cp.async.wait_group 0;" ::: "memory");
        __syncthreads();
        if (c + 2 < NC) {
            stsA((c + 2) % NSTAGE);
            issueB(c + 2, (c + 2) % NSTAGE);
            if (c + 3 < NC) ldgA(c + 3);
        }

        const uint32_t aB = sA + slot * A_BYTES;
        const uint32_t bB = sB + slot * B_BYTES;
#pragma unroll
        for (int ks = 0; ks < 4; ks++) {
            const int kofs = ks * 16;
            uint32_t afr[2][4];
#pragma unroll
            for (int mi = 0; mi < 2; mi++) {
                int row = wm * 32 + mi * 16 + ml + (tl & 1) * 8;
                int col = kofs + (tl >> 1) * 8;
                ldsm4(afr[mi], aB + (uint32_t)((row * ASTR + col) * 2));
            }
#pragma unroll
            for (int jj = 0; jj < 4; jj++) {
                uint32_t bfr[4];
                int rn  = wn * 64 + jj * 16 + ml + (tl >> 1) * 8;
                int col = kofs + (tl & 1) * 8;
                ldsm4(bfr, bB + (uint32_t)((rn * ASTR + col) * 2));
#pragma unroll
                for (int mi = 0; mi < 2; mi++) {
                    mma16816(acc[mi][2 * jj],     afr[mi], bfr);
                    mma16816(acc[mi][2 * jj + 1], afr[mi], bfr + 2);
                }
            }
        }
    }

    const int g  = lane >> 2;
    const int t2 = (lane & 3) * 2;

    if constexpr (EPI == EPI_GELU) {
#pragma unroll
        for (int mi = 0; mi < 2; mi++) {
            const int r0 = wm * 32 + mi * 16 + g;
#pragma unroll
            for (int nj = 0; nj < 8; nj++) {
                const int col = wn * 64 + nj * 8 + t2;
                const float b0v = bias[col], b1v = bias[col + 1];
                float x0 = gelu_f(acc[mi][nj][0] + b0v);
                float x1 = gelu_f(acc[mi][nj][1] + b1v);
                *(__half2*)(out + (size_t)(m0 + r0) * ldout + n0g + col) = __floats2half2_rn(x0, x1);
                float x2 = gelu_f(acc[mi][nj][2] + b0v);
                float x3 = gelu_f(acc[mi][nj][3] + b1v);
                *(__half2*)(out + (size_t)(m0 + r0 + 8) * ldout + n0g + col) = __floats2half2_rn(x2, x3);
            }
        }
    } else {  // EPI_LN2
        __syncthreads();
        float* sb = (float*)smem;
#pragma unroll
        for (int mi = 0; mi < 2; mi++) {
            const int r0 = wm * 32 + mi * 16 + g;
#pragma unroll
            for (int nj = 0; nj < 8; nj++) {
                const int col = wn * 64 + nj * 8 + t2;
                const float b0v = bias[col], b1v = bias[col + 1];
                sb[r0 * 264 + col]           = acc[mi][nj][0] + b0v + h_res[(size_t)(m0 + r0) * HD + col];
                sb[r0 * 264 + col + 1]       = acc[mi][nj][1] + b1v + h_res[(size_t)(m0 + r0) * HD + col + 1];
                sb[(r0 + 8) * 264 + col]     = acc[mi][nj][2] + b0v + h_res[(size_t)(m0 + r0 + 8) * HD + col];
                sb[(r0 + 8) * 264 + col + 1] = acc[mi][nj][3] + b1v + h_res[(size_t)(m0 + r0 + 8) * HD + col + 1];
            }
        }
        __syncthreads();
        for (int rr = 0; rr < 8; rr++) {
            const int row = warp * 8 + rr;
            float s = 0.f, s2 = 0.f;
#pragma unroll
            for (int i = 0; i < 8; i++) {
                float v = sb[row * 264 + lane + i * 32];
                s += v; s2 += v * v;
            }
#pragma unroll
            for (int off = 16; off; off >>= 1) {
                s  += __shfl_xor_sync(0xffffffffu, s, off);
                s2 += __shfl_xor_sync(0xffffffffu, s2, off);
            }
            const float mu  = s * (1.0f / HD);
            const float var = s2 * (1.0f / HD) - mu * mu;
            const float rs  = rsqrtf(var + 1e-5f);
#pragma unroll
            for (int i = 0; i < 8; i++) {
                const int cc = lane + i * 32;
                const float v = sb[row * 264 + cc];
                outf[(size_t)(m0 + row) * HD + cc] = (v - mu) * rs * ln_g[cc] + ln_b[cc];
            }
        }
    }
}

// ---------------- fused edge GEMM2+GEMM3 ----------------
// X3 = gelu(gelu(X1 @ W1 + b1) @ W2 + b2), X2 kept in smem. In-place: out == Xin rows.
__global__ void __launch_bounds__(512, 1)
gemm_fused23(const __half* __restrict__ Xin,
             const __half* __restrict__ W1, const float* __restrict__ b1,
             const __half* __restrict__ W2, const float* __restrict__ b2,
             __half* __restrict__ out) {
    extern __shared__ char smem[];
    __half* As2 = (__half*)smem;   // A2 buffer, 4 chunks of A_BYTES
    const int tid = threadIdx.x;
    const int m0  = blockIdx.x * BM;

    const uint32_t sA  = (uint32_t)__cvta_generic_to_shared(smem);
    const uint32_t sB  = sA + NSTAGE * A_BYTES;
    const uint32_t sA2 = sA + A2_OFF;
    const uint32_t sB2 = sA + B2_OFF;

    const int lane = tid & 31, warp = tid >> 5;
    const int wm = warp & 3, wn = warp >> 2;
    const int ml = lane & 7, tl = lane >> 3;

    auto issue1 = [&](int kc, int slot) {    // stage-1: A=Xin, B=W1, K=256
#pragma unroll
        for (int i = 0; i < 2; i++) {
            int idx = tid + i * 512;
            int r = idx >> 3, q = idx & 7;
            cpasync16(sA + slot * A_BYTES + (uint32_t)((r * ASTR + q * 8) * 2),
                      Xin + (size_t)(m0 + r) * 256 + kc * BK + q * 8);
        }
#pragma unroll
        for (int i = 0; i < 4; i++) {
            int idx = tid + i * 512;
            int r = idx >> 3, q = idx & 7;
            cpasync16(sB + slot * B_BYTES + (uint32_t)((r * ASTR + q * 8) * 2),
                      W1 + (size_t)r * 256 + kc * BK + q * 8);
        }
        cp_commit();
    };
    auto issue2 = [&](int kc, int slot) {    // stage-2: B=W2 only, K=256
#pragma unroll
        for (int i = 0; i < 4; i++) {
            int idx = tid + i * 512;
            int r = idx >> 3, q = idx & 7;
            cpasync16(sB2 + slot * B_BYTES + (uint32_t)((r * ASTR + q * 8) * 2),
                      W2 + (size_t)r * 256 + kc * BK + q * 8);
        }
        cp_commit();
    };

    float acc[2][8][4];
#pragma unroll
    for (int mi = 0; mi < 2; mi++)
#pragma unroll
        for (int nj = 0; nj < 8; nj++)
#pragma unroll
            for (int j = 0; j < 4; j++) acc[mi][nj][j] = 0.f;

    // ---- mainloop 1 (NC=4, 3-stage) ----
    issue1(0, 0);
    issue1(1, 1);
    for (int c = 0; c < 4; c++) {
        const int slot = c % NSTAGE;
        if (c + 1 < 4) asm volatile("cp.async.wait_group 1;" ::: "memory");
        else           asm volatile("cp.async.wait_group 0;" ::: "memory");
        __syncthreads();
        if (c + 2 < 4) issue1(c + 2, (c + 2) % NSTAGE);

        const uint32_t aB = sA + slot * A_BYTES;
        const uint32_t bB = sB + slot * B_BYTES;
#pragma unroll
        for (int ks = 0; ks < 4; ks++) {
            const int kofs = ks * 16;
            uint32_t afr[2][4];
#pragma unroll
            for (int mi = 0; mi < 2; mi++) {
                int row = wm * 32 + mi * 16 + ml + (tl & 1) * 8;
                int col = kofs + (tl >> 1) * 8;
                ldsm4(afr[mi], aB + (uint32_t)((row * ASTR + col) * 2));
            }
#pragma unroll
            for (int jj = 0; jj < 4; jj++) {
                uint32_t bfr[4];
                int rn  = wn * 64 + jj * 16 + ml + (tl >> 1) * 8;
                int col = kofs + (tl & 1) * 8;
                ldsm4(bfr, bB + (uint32_t)((rn * ASTR + col) * 2));
#pragma unroll
                for (int mi = 0; mi < 2; mi++) {
                    mma16816(acc[mi][2 * jj],     afr[mi], bfr);
                    mma16816(acc[mi][2 * jj + 1], afr[mi], bfr + 2);
                }
            }
        }
    }

    // ---- X2 = gelu(acc + b1) into smem A2 (ldsm layout, chunk = wn) ----
    __syncthreads();   // all ldsm reads of stage-1 buffers done before overwrite
    {
        const int g  = lane >> 2;
        const int t2 = (lane & 3) * 2;
#pragma unroll
        for (int mi = 0; mi < 2; mi++) {
            const int r0 = wm * 32 + mi * 16 + g;
#pragma unroll
            for (int nj = 0; nj < 8; nj++) {
                const int cl  = nj * 8 + t2;            // col within chunk wn
                const int col = wn * 64 + cl;           // global col (= stage-2 k)
                const float b0v = b1[col], b1v = b1[col + 1];
                __half2 v01 = __floats2half2_rn(gelu_f(acc[mi][nj][0] + b0v),
                                                gelu_f(acc[mi][nj][1] + b1v));
                __half2 v23 = __floats2half2_rn(gelu_f(acc[mi][nj][2] + b0v),
                                                gelu_f(acc[mi][nj][3] + b1v));
                *(__half2*)(As2 + wn * (A_BYTES / 2) + r0 * ASTR + cl)       = v01;
                *(__half2*)(As2 + wn * (A_BYTES / 2) + (r0 + 8) * ASTR + cl) = v23;
                // reset accumulator for stage 2
                acc[mi][nj][0] = acc[mi][nj][1] = acc[mi][nj][2] = acc[mi][nj][3] = 0.f;
            }
        }
    }
    __syncthreads();   // A2 visible to all; stage-1 B region now reusable for B2
    issue2(0, 0);
    issue2(1, 1);

    // ---- mainloop 2 (NC=4, 2-stage, A from smem) ----
    for (int c = 0; c < 4; c++) {
        const int slot = c & 1;
        if (c + 1 < 4) asm volatile("cp.async.wait_group 1;" ::: "memory");
        else           asm volatile("cp.async.wait_group 0;" ::: "memory");
        __syncthreads();

        const uint32_t aB = sA2 + c * A_BYTES;
        const uint32_t bB = sB2 + slot * B_BYTES;
#pragma unroll
        for (int ks = 0; ks < 4; ks++) {
            const int kofs = ks * 16;
            uint32_t afr[2][4];
#pragma unroll
            for (int mi = 0; mi < 2; mi++) {
                int row = wm * 32 + mi * 16 + ml + (tl & 1) * 8;
                int col = kofs + (tl >> 1) * 8;
                ldsm4(afr[mi], aB + (uint32_t)((row * ASTR + col) * 2));
            }
#pragma unroll
            for (int jj = 0; jj < 4; jj++) {
                uint32_t bfr[4];
                int rn  = wn * 64 + jj * 16 + ml + (tl >> 1) * 8;
                int col = kofs + (tl & 1) * 8;
                ldsm4(bfr, bB + (uint32_t)((rn * ASTR + col) * 2));
#pragma unroll
                for (int mi = 0; mi < 2; mi++) {
                    mma16816(acc[mi][2 * jj],     afr[mi], bfr);
                    mma16816(acc[mi][2 * jj + 1], afr[mi], bfr + 2);
                }
            }
        }
        __syncthreads();   // all reads of slot done before reissue
        if (c + 2 < 4) issue2(c + 2, slot);
    }

    // ---- epilogue: X3 = gelu(acc + b2) -> gmem (in-place rows of Xin) ----
    {
        const int g  = lane >> 2;
        const int t2 = (lane & 3) * 2;
#pragma unroll
        for (int mi = 0; mi < 2; mi++) {
            const int r0 = wm * 32 + mi * 16 + g;
#pragma unroll
            for (int nj = 0; nj < 8; nj++) {
                const int col = wn * 64 + nj * 8 + t2;
                const float b0v = b2[col], b1v = b2[col + 1];
                float x0 = gelu_f(acc[mi][nj][0] + b0v);
                float x1 = gelu_f(acc[mi][nj][1] + b1v);
                *(__half2*)(out + (size_t)(m0 + r0) * HD + col) = __floats2half2_rn(x0, x1);
                float x2 = gelu_f(acc[mi][nj][2] + b0v);
                float x3 = gelu_f(acc[mi][nj][3] + b1v);
                *(__half2*)(out + (size_t)(m0 + r0 + 8) * HD + col) = __floats2half2_rn(x2, x3);
            }
        }
    }
}

// ---------------- host launcher ----------------
extern "C" void kernel_launch(void* const* d_in, const int* in_sizes, int n_in,
                              void* d_out, int out_size) {
    const float* h_V  = (const float*)d_in[0];
    const float* h_E  = (const float*)d_in[1];
    const void*  eidx = d_in[2];
    const float* m0w  = (const float*)d_in[3];
    const float* m0b  = (const float*)d_in[4];
    const float* m1w  = (const float*)d_in[5];
    const float* m1b  = (const float*)d_in[6];
    const float* m2w  = (const float*)d_in[7];
    const float* m2b  = (const float*)d_in[8];
    const float* d0w  = (const float*)d_in[9];
    const float* d0b  = (const float*)d_in[10];
    const float* d1w  = (const float*)d_in[11];
    const float* d1b  = (const float*)d_in[12];
    const float* d2w  = (const float*)d_in[13];
    const float* d2b  = (const float*)d_in[14];
    const float* ln1g = (const float*)d_in[15];
    const float* ln1b = (const float*)d_in[16];
    const float* ln2g = (const float*)d_in[17];
    const float* ln2b = (const float*)d_in[18];
    float* outf = (float*)d_out;
    (void)n_in; (void)out_size; (void)in_sizes;

    void *pWT, *pXa, *pXb, *pH, *pHH;
    cudaGetSymbolAddress(&pWT, g_WT);
    cudaGetSymbolAddress(&pXa, g_Xa);
    cudaGetSymbolAddress(&pXb, g_Xb);
    cudaGetSymbolAddress(&pH,  g_h);
    cudaGetSymbolAddress(&pHH, g_hh);
    __half* WT = (__half*)pWT;
    __half* Xa = (__half*)pXa;
    __half* Xb = (__half*)pXb;
    float*  hb = (float*)pH;
    __half* hh = (__half*)pHH;

    cudaFuncSetAttribute(gemm_kernel<512,  EPI_GELU, true>,  cudaFuncAttributeMaxDynamicSharedMemorySize, SMEM_MMA);
    cudaFuncSetAttribute(gemm_kernel<256,  EPI_GELU, false>, cudaFuncAttributeMaxDynamicSharedMemorySize, SMEM_MMA);
    cudaFuncSetAttribute(gemm_kernel<1024, EPI_GELU, false>, cudaFuncAttributeMaxDynamicSharedMemorySize, SMEM_MMA);
    cudaFuncSetAttribute(gemm_kernel<1024, EPI_LN2,  false>, cudaFuncAttributeMaxDynamicSharedMemorySize, SMEM_MMA);
    cudaFuncSetAttribute(gemm_fused23, cudaFuncAttributeMaxDynamicSharedMemorySize, SMEM_MMA);

    // --- launch order: GEMM1 is the 4th launch (observed ncu capture slot) ---
    detect_idx_kernel<<<1, 32>>>((const int*)eidx);                                // 1
    prep_wt_kernel<<<(512 * 256 + 255) / 256, 256>>>(m0w, WT + WOFF_M0, 512, 256); // 2
    zero_cnt_kernel<<<NNODES / 256, 256>>>();                                      // 3
    gemm_kernel<512, EPI_GELU, true><<<dim3(EDGES / BM, 1), 512, SMEM_MMA>>>(      // 4 <- profiled
        h_E, WT + WOFF_M0, m0b, Xa, HD, nullptr, nullptr, nullptr, nullptr);

    count_kernel<<<EDGES / 256, 256>>>(eidx);
    scan_kernel<<<1, 1024>>>();
    fill_kernel<<<EDGES / 256, 256>>>(eidx);
    prep_wt_kernel<<<(256  * 256  + 255) / 256, 256>>>(m1w, WT + WOFF_M1, 256,  256);
    prep_wt_kernel<<<(256  * 256  + 255) / 256, 256>>>(m2w, WT + WOFF_M2, 256,  256);
    prep_wt_kernel<<<(256  * 1024 + 255) / 256, 256>>>(d0w, WT + WOFF_D0, 256,  1024);
    prep_wt_kernel<<<(1024 * 1024 + 255) / 256, 256>>>(d1w, WT + WOFF_D1, 1024, 1024);
    prep_wt_kernel<<<(1024 * 256  + 255) / 256, 256>>>(d2w, WT + WOFF_D2, 1024, 256);

    // --- fused edge MLP layers 2+3 (in-place on Xa) ---
    gemm_fused23<<<EDGES / BM, 512, SMEM_MMA>>>(
        Xa, WT + WOFF_M1, m1b, WT + WOFF_M2, m2b, Xa);

    // --- scatter-sum via CSR gather, fused with LN1 ---
    gather_ln1_kernel<<<NNODES, 256>>>(Xa, h_V, ln1g, ln1b, hb, hh);

    // --- dense MLP ---
    gemm_kernel<256, EPI_GELU, false><<<dim3(NNODES / BM, 4), 512, SMEM_MMA>>>(
        hh, WT + WOFF_D0, d0b, Xb, DD, nullptr, nullptr, nullptr, nullptr);
    gemm_kernel<1024, EPI_GELU, false><<<dim3(NNODES / BM, 4), 512, SMEM_MMA>>>(
        Xb, WT + WOFF_D1, d1b, Xa, DD, nullptr, nullptr, nullptr, nullptr);
    gemm_kernel<1024, EPI_LN2, false><<<dim3(NNODES / BM, 1), 512, SMEM_MMA>>>(
        Xa, WT + WOFF_D2, d2b, nullptr, 0, hb, ln2g, ln2b, outf);
}